// round 2
// baseline (speedup 1.0000x reference)
#include <cuda_runtime.h>

// ---------------------------------------------------------------------------
// AtlasAttention: q = X @ Wq ; poly expand per head ; MLP(256->512->256) read;
// out = mem[:, :64] folded back to [B,S,768].
//
// Key algebraic reductions:
//  * only first 64 cols of W2/b2 matter  (K2-GEMM N: 256 -> 64)
//  * constant poly block (coeffs[0]*ones) folds into an effective bias b1_eff
//    (K1-GEMM K: 256 -> 192)
// ---------------------------------------------------------------------------

#define TOKENS   8192      // 4 * 2048
#define HIDDEN   768
#define NHEADS   12
#define HD       64
#define MEMHID   512
#define POLYK    192       // effective K after folding constant block
#define ROWS_TOT (TOKENS * NHEADS)   // 98304

__device__ float g_Q[TOKENS * HIDDEN];   // 25 MB scratch (BSS, no alloc)
__device__ float g_b1eff[MEMHID];

// ---------------------------------------------------------------------------
// prep: b1_eff[j] = b1[j] + coeffs[0] * sum_{d<64} W1[d, j]
// ---------------------------------------------------------------------------
__global__ void prep_b1eff(const float* __restrict__ W1,
                           const float* __restrict__ b1,
                           const float* __restrict__ coeffs) {
    int j = threadIdx.x;
    if (j < MEMHID) {
        float s = 0.f;
        #pragma unroll 8
        for (int d = 0; d < HD; ++d) s += W1[d * MEMHID + j];
        g_b1eff[j] = b1[j] + coeffs[0] * s;
    }
}

// ---------------------------------------------------------------------------
// SGEMM: C[M,N] = A[M,K] @ B[K,N], row-major. BM=BN=128, BK=8, 256 thr, 8x8.
// Requires M%128==0, N%128==0, K%8==0 (8192/768/768: OK).
// ---------------------------------------------------------------------------
__global__ __launch_bounds__(256) void sgemm128(const float* __restrict__ A,
                                                const float* __restrict__ B,
                                                float* __restrict__ C,
                                                int M, int N, int K) {
    __shared__ float As[8][128];   // transposed A tile
    __shared__ float Bs[8][128];
    const int tid = threadIdx.x;
    const int tx = tid & 15, ty = tid >> 4;
    const int row0 = blockIdx.y * 128, col0 = blockIdx.x * 128;
    const int aRow = tid >> 1, aCol = (tid & 1) * 4;
    const int bRow = tid >> 5, bCol = (tid & 31) * 4;
    const float* Ap = A + (long)(row0 + aRow) * K + aCol;
    const float* Bp = B + (long)bRow * N + col0 + bCol;

    float acc[8][8];
    #pragma unroll
    for (int i = 0; i < 8; ++i)
        #pragma unroll
        for (int j = 0; j < 8; ++j) acc[i][j] = 0.f;

    for (int kt = 0; kt < K; kt += 8) {
        float4 a = *(const float4*)(Ap + kt);
        As[aCol + 0][aRow] = a.x;
        As[aCol + 1][aRow] = a.y;
        As[aCol + 2][aRow] = a.z;
        As[aCol + 3][aRow] = a.w;
        *(float4*)&Bs[bRow][bCol] = *(const float4*)(Bp + (long)kt * N);
        __syncthreads();
        #pragma unroll
        for (int k = 0; k < 8; ++k) {
            float ra[8], rb[8];
            *(float4*)&ra[0] = *(const float4*)&As[k][ty * 8];
            *(float4*)&ra[4] = *(const float4*)&As[k][ty * 8 + 4];
            *(float4*)&rb[0] = *(const float4*)&Bs[k][tx * 8];
            *(float4*)&rb[4] = *(const float4*)&Bs[k][tx * 8 + 4];
            #pragma unroll
            for (int i = 0; i < 8; ++i)
                #pragma unroll
                for (int j = 0; j < 8; ++j)
                    acc[i][j] += ra[i] * rb[j];
        }
        __syncthreads();
    }
    #pragma unroll
    for (int i = 0; i < 8; ++i) {
        float* c = C + (long)(row0 + ty * 8 + i) * N + col0 + tx * 8;
        *(float4*)c       = make_float4(acc[i][0], acc[i][1], acc[i][2], acc[i][3]);
        *(float4*)(c + 4) = make_float4(acc[i][4], acc[i][5], acc[i][6], acc[i][7]);
    }
}

// ---------------------------------------------------------------------------
// Fused poly + MLP. One CTA = 64 (token,head) rows.
//   Pt  [192][64] poly features, transposed (K-major)    48 KB
//   Ws  [16][64]  streamed W1 tile                        4 KB
//   W2s [64][64]  W2 chunk (cols 0..63)                  16 KB
//   Hs  [64][65]  ReLU(hidden) chunk, transposed       16.25 KB
// Per chunk hc (8 chunks of 64 hidden units):
//   GEMM1: acc1[64x64] = Pt^T @ W1[64+k, hc*64+n]  (K=192, bias=b1_eff)
//   ReLU -> Hs ; GEMM2: acc2[64x64] += Hs^T @ W2s  (K=64)
// ---------------------------------------------------------------------------
__global__ __launch_bounds__(256) void fused_poly_mlp(
    const float* __restrict__ W1, const float* __restrict__ W2,
    const float* __restrict__ b2, const float* __restrict__ coeffs,
    float* __restrict__ out) {
    extern __shared__ float smem[];
    float* Pt  = smem;                 // 192*64
    float* Ws  = Pt + POLYK * 64;      // 16*64
    float* W2s = Ws + 16 * 64;         // 64*64
    float* Hs  = W2s + 64 * 64;        // 64*65

    const int tid = threadIdx.x;
    const int tx = tid & 15, ty = tid >> 4;
    const int r0 = blockIdx.x * 64;

    const float c1 = coeffs[1], c2 = coeffs[2], c3 = coeffs[3];

    // ---- phase 0: poly features, transposed into Pt[k][m] ----
    {
        const int d  = tid & 63;
        const int mg = tid >> 6;       // 0..3
        #pragma unroll 4
        for (int m = mg; m < 64; m += 4) {
            const int r = r0 + m;
            const int t = r / NHEADS, hd = r % NHEADS;
            float x = g_Q[t * HIDDEN + hd * HD + d];
            x = fminf(fmaxf(x, -10.f), 10.f);
            const float x2 = x * x;
            float f1 = c1 * x, f2 = c2 * x2, f3 = c3 * x2 * x;
            f1 = fminf(fmaxf(f1, -1e6f), 1e6f);
            f2 = fminf(fmaxf(f2, -1e6f), 1e6f);
            f3 = fminf(fmaxf(f3, -1e6f), 1e6f);
            Pt[d * 64 + m]         = f1;
            Pt[(64 + d) * 64 + m]  = f2;
            Pt[(128 + d) * 64 + m] = f3;
        }
    }

    float acc2[4][4];
    #pragma unroll
    for (int i = 0; i < 4; ++i)
        #pragma unroll
        for (int j = 0; j < 4; ++j) acc2[i][j] = 0.f;

    const int wRow = tid >> 4, wCol = (tid & 15) * 4;

    for (int hc = 0; hc < 8; ++hc) {
        // ---- GEMM1: hidden chunk [64 rows x 64 hid], K = 192 ----
        float acc1[4][4];
        {
            float bj[4];
            *(float4*)bj = *(const float4*)&g_b1eff[hc * 64 + tx * 4];
            #pragma unroll
            for (int i = 0; i < 4; ++i)
                #pragma unroll
                for (int j = 0; j < 4; ++j) acc1[i][j] = bj[j];
        }
        for (int kt = 0; kt < 12; ++kt) {
            __syncthreads();           // Ws / (Hs,W2s on first iter) reuse guard
            *(float4*)&Ws[wRow * 64 + wCol] =
                *(const float4*)&W1[(HD + kt * 16 + wRow) * MEMHID + hc * 64 + wCol];
            __syncthreads();
            #pragma unroll
            for (int k = 0; k < 16; ++k) {
                float ra[4], rb[4];
                *(float4*)ra = *(const float4*)&Pt[(kt * 16 + k) * 64 + ty * 4];
                *(float4*)rb = *(const float4*)&Ws[k * 64 + tx * 4];
                #pragma unroll
                for (int i = 0; i < 4; ++i)
                    #pragma unroll
                    for (int j = 0; j < 4; ++j)
                        acc1[i][j] += ra[i] * rb[j];
            }
        }
        __syncthreads();
        // ---- ReLU + transpose into Hs; load W2 chunk ----
        #pragma unroll
        for (int i = 0; i < 4; ++i)
            #pragma unroll
            for (int j = 0; j < 4; ++j)
                Hs[(tx * 4 + j) * 65 + ty * 4 + i] = fmaxf(acc1[i][j], 0.f);
        #pragma unroll
        for (int it = 0; it < 4; ++it) {
            const int rr = wRow + it * 16;
            *(float4*)&W2s[rr * 64 + wCol] =
                *(const float4*)&W2[(hc * 64 + rr) * 256 + wCol];
        }
        __syncthreads();
        // ---- GEMM2: acc2 += Hs^T @ W2s, K = 64 ----
        #pragma unroll 8
        for (int k = 0; k < 64; ++k) {
            float ra[4], rb[4];
            ra[0] = Hs[k * 65 + ty * 4 + 0];
            ra[1] = Hs[k * 65 + ty * 4 + 1];
            ra[2] = Hs[k * 65 + ty * 4 + 2];
            ra[3] = Hs[k * 65 + ty * 4 + 3];
            *(float4*)rb = *(const float4*)&W2s[k * 64 + tx * 4];
            #pragma unroll
            for (int i = 0; i < 4; ++i)
                #pragma unroll
                for (int j = 0; j < 4; ++j)
                    acc2[i][j] += ra[i] * rb[j];
        }
    }

    // ---- epilogue: out[t, hd*64 + n] = acc2 + b2[n] ----
    float bo[4];
    *(float4*)bo = *(const float4*)&b2[tx * 4];
    #pragma unroll
    for (int i = 0; i < 4; ++i) {
        const int r = r0 + ty * 4 + i;
        const int t = r / NHEADS, hd = r % NHEADS;
        float4 v = make_float4(acc2[i][0] + bo[0], acc2[i][1] + bo[1],
                               acc2[i][2] + bo[2], acc2[i][3] + bo[3]);
        *(float4*)&out[t * HIDDEN + hd * HD + tx * 4] = v;
    }
}

// ---------------------------------------------------------------------------
// launch
// ---------------------------------------------------------------------------
extern "C" void kernel_launch(void* const* d_in, const int* in_sizes, int n_in,
                              void* d_out, int out_size) {
    const float* X      = (const float*)d_in[0];   // [4,2048,768]
    const float* Wq     = (const float*)d_in[1];   // [768,768]
    const float* coeffs = (const float*)d_in[2];   // [4]
    const float* W1     = (const float*)d_in[3];   // [256,512]
    const float* b1     = (const float*)d_in[4];   // [512]
    const float* W2     = (const float*)d_in[5];   // [512,256]
    const float* b2     = (const float*)d_in[6];   // [256]
    float* out = (float*)d_out;

    float* Qp = nullptr;
    cudaGetSymbolAddress((void**)&Qp, g_Q);

    const int fused_smem = (POLYK * 64 + 16 * 64 + 64 * 64 + 64 * 65) * 4; // 86272 B
    cudaFuncSetAttribute(fused_poly_mlp,
                         cudaFuncAttributeMaxDynamicSharedMemorySize, fused_smem);

    prep_b1eff<<<1, MEMHID>>>(W1, b1, coeffs);

    dim3 g1(HIDDEN / 128, TOKENS / 128);
    sgemm128<<<g1, 256>>>(X, Wq, Qp, TOKENS, HIDDEN, HIDDEN);

    fused_poly_mlp<<<ROWS_TOT / 64, 256, fused_smem>>>(W1, W2, b2, coeffs, out);
}

// round 3
// speedup vs baseline: 1.0309x; 1.0309x over previous
#include <cuda_runtime.h>

// ---------------------------------------------------------------------------
// AtlasAttention, round 3: packed-f32x2 (FFMA2) 3-kernel pipeline.
//   K1 qproj   : g_Q = X @ Wq                       [8192x768x768]
//   K2 polymlp1: g_H = relu(poly(g_Q) @ W1' + b1')  [98304x512, K=192]
//   K3 mlp2    : out = g_H @ W2[:,:64] + b2[:64]    [98304x64,  K=512]
// Algebraic cuts kept: const poly block folded into b1_eff (K 256->192),
// only first 64 cols of W2/b2 used (N 256->64).
// All GEMMs: 8x8 microtile, fma.rn.f32x2 accumulators (2 flop/lane/issue).
// ---------------------------------------------------------------------------

#define TOKENS   8192
#define HIDDEN   768
#define NHEADS   12
#define HD       64
#define MEMHID   512
#define ROWS_TOT (TOKENS * NHEADS)   // 98304

__device__ float g_Q[TOKENS * HIDDEN];     // 25 MB
__device__ float g_H[ROWS_TOT * MEMHID];   // 201 MB
__device__ float g_b1eff[MEMHID];

typedef unsigned long long u64;

__device__ __forceinline__ u64 pack2(float lo, float hi) {
    u64 r; asm("mov.b64 %0, {%1, %2};" : "=l"(r) : "f"(lo), "f"(hi)); return r;
}
__device__ __forceinline__ u64 dup2(float x) {
    u64 r; asm("mov.b64 %0, {%1, %1};" : "=l"(r) : "f"(x)); return r;
}
__device__ __forceinline__ void fma2(u64& d, u64 a, u64 b) {
    asm("fma.rn.f32x2 %0, %1, %2, %0;" : "+l"(d) : "l"(a), "l"(b));
}
__device__ __forceinline__ float2 unp2(u64 v) {
    float2 f; asm("mov.b64 {%0, %1}, %2;" : "=f"(f.x), "=f"(f.y) : "l"(v)); return f;
}

// ---------------------------------------------------------------------------
// prep: b1_eff[j] = b1[j] + coeffs[0] * sum_{d<64} W1[d, j]
// ---------------------------------------------------------------------------
__global__ void prep_b1eff(const float* __restrict__ W1,
                           const float* __restrict__ b1,
                           const float* __restrict__ coeffs) {
    int j = threadIdx.x;
    if (j < MEMHID) {
        float s = 0.f;
        #pragma unroll 8
        for (int d = 0; d < HD; ++d) s += W1[d * MEMHID + j];
        g_b1eff[j] = b1[j] + coeffs[0] * s;
    }
}

// ---------------------------------------------------------------------------
// shared 8x8 f32x2 micro-kernel step (acc[8][4] of packed pairs)
// ---------------------------------------------------------------------------
#define MICRO_STEP(As, Bs, k, ty, tx, acc)                                   \
    {                                                                        \
        float ra[8];                                                         \
        *(float4*)&ra[0] = *(const float4*)&As[k][(ty) * 8];                 \
        *(float4*)&ra[4] = *(const float4*)&As[k][(ty) * 8 + 4];             \
        const u64* bp = (const u64*)&Bs[k][(tx) * 8];                        \
        u64 b0 = bp[0], b1 = bp[1], b2 = bp[2], b3 = bp[3];                  \
        _Pragma("unroll")                                                    \
        for (int i = 0; i < 8; ++i) {                                        \
            u64 ad = dup2(ra[i]);                                            \
            fma2(acc[i][0], ad, b0);                                         \
            fma2(acc[i][1], ad, b1);                                         \
            fma2(acc[i][2], ad, b2);                                         \
            fma2(acc[i][3], ad, b3);                                         \
        }                                                                    \
    }

// ---------------------------------------------------------------------------
// K1: g_Q = X @ Wq. 128x128x8 tiles, 256 threads, 8x8 micro, f32x2.
// ---------------------------------------------------------------------------
__global__ __launch_bounds__(256) void qproj(const float* __restrict__ A,
                                             const float* __restrict__ B) {
    __shared__ float As[8][128];
    __shared__ float Bs[8][128];
    const int tid = threadIdx.x;
    const int tx = tid & 15, ty = tid >> 4;
    const int row0 = blockIdx.y * 128, col0 = blockIdx.x * 128;
    const int aRow = tid >> 1, aCol = (tid & 1) * 4;
    const int bRow = tid >> 5, bCol = (tid & 31) * 4;
    const float* Ap = A + (long)(row0 + aRow) * HIDDEN + aCol;
    const float* Bp = B + (long)bRow * HIDDEN + col0 + bCol;

    u64 acc[8][4];
    #pragma unroll
    for (int i = 0; i < 8; ++i)
        #pragma unroll
        for (int j = 0; j < 4; ++j) acc[i][j] = 0ull;

    for (int kt = 0; kt < HIDDEN; kt += 8) {
        float4 a = *(const float4*)(Ap + kt);
        As[aCol + 0][aRow] = a.x;
        As[aCol + 1][aRow] = a.y;
        As[aCol + 2][aRow] = a.z;
        As[aCol + 3][aRow] = a.w;
        *(float4*)&Bs[bRow][bCol] = *(const float4*)(Bp + (long)kt * HIDDEN);
        __syncthreads();
        #pragma unroll
        for (int k = 0; k < 8; ++k) MICRO_STEP(As, Bs, k, ty, tx, acc)
        __syncthreads();
    }
    #pragma unroll
    for (int i = 0; i < 8; ++i) {
        float* c = g_Q + (long)(row0 + ty * 8 + i) * HIDDEN + col0 + tx * 8;
        float2 p0 = unp2(acc[i][0]), p1 = unp2(acc[i][1]);
        float2 p2 = unp2(acc[i][2]), p3 = unp2(acc[i][3]);
        *(float4*)c       = make_float4(p0.x, p0.y, p1.x, p1.y);
        *(float4*)(c + 4) = make_float4(p2.x, p2.y, p3.x, p3.y);
    }
}

// ---------------------------------------------------------------------------
// K2: g_H = relu(P @ W1[64:,:] + b1_eff), P[r, 64a+d] = clip(c_{a+1} x^{a+1}).
// Poly features generated in the A-tile loader, phase-unrolled by power a.
// M=98304, N=512, K=192. 128x128x8 tiles, 256 threads, 8x8 micro, f32x2.
// ---------------------------------------------------------------------------
__global__ __launch_bounds__(256) void poly_mlp1(const float* __restrict__ W1,
                                                 const float* __restrict__ coeffs) {
    __shared__ float As[8][128];
    __shared__ float Bs[8][128];
    const int tid = threadIdx.x;
    const int tx = tid & 15, ty = tid >> 4;
    const int row0 = blockIdx.y * 128, col0 = blockIdx.x * 128;
    const int aRow = tid >> 1, aCol = (tid & 1) * 4;
    const int bRow = tid >> 5, bCol = (tid & 31) * 4;

    const int r = row0 + aRow;
    const int t = r / NHEADS, hd = r % NHEADS;
    const float* xbase = g_Q + (long)t * HIDDEN + hd * HD;
    const float* Bp = W1 + (long)(HD + bRow) * MEMHID + col0 + bCol;

    u64 acc[8][4];
    {   // bias init
        float bj[8];
        *(float4*)&bj[0] = *(const float4*)&g_b1eff[col0 + tx * 8];
        *(float4*)&bj[4] = *(const float4*)&g_b1eff[col0 + tx * 8 + 4];
        u64 p0 = pack2(bj[0], bj[1]), p1 = pack2(bj[2], bj[3]);
        u64 p2 = pack2(bj[4], bj[5]), p3 = pack2(bj[6], bj[7]);
        #pragma unroll
        for (int i = 0; i < 8; ++i) {
            acc[i][0] = p0; acc[i][1] = p1; acc[i][2] = p2; acc[i][3] = p3;
        }
    }

    #pragma unroll
    for (int a = 0; a < 3; ++a) {
        const float ca = coeffs[a + 1];
        for (int kb = 0; kb < 8; ++kb) {
            const int d = kb * 8 + aCol;
            float4 xv = *(const float4*)(xbase + d);
            float f[4];
            const float xs[4] = {xv.x, xv.y, xv.z, xv.w};
            #pragma unroll
            for (int e = 0; e < 4; ++e) {
                float x = fminf(fmaxf(xs[e], -10.f), 10.f);
                float p = x;
                if (a >= 1) p *= x;
                if (a >= 2) p *= x;
                f[e] = fminf(fmaxf(ca * p, -1e6f), 1e6f);
            }
            As[aCol + 0][aRow] = f[0];
            As[aCol + 1][aRow] = f[1];
            As[aCol + 2][aRow] = f[2];
            As[aCol + 3][aRow] = f[3];
            *(float4*)&Bs[bRow][bCol] =
                *(const float4*)(Bp + (long)(a * 64 + kb * 8) * MEMHID);
            __syncthreads();
            #pragma unroll
            for (int k = 0; k < 8; ++k) MICRO_STEP(As, Bs, k, ty, tx, acc)
            __syncthreads();
        }
    }
    #pragma unroll
    for (int i = 0; i < 8; ++i) {
        float* c = g_H + (long)(row0 + ty * 8 + i) * MEMHID + col0 + tx * 8;
        float2 p0 = unp2(acc[i][0]), p1 = unp2(acc[i][1]);
        float2 p2 = unp2(acc[i][2]), p3 = unp2(acc[i][3]);
        *(float4*)c       = make_float4(fmaxf(p0.x, 0.f), fmaxf(p0.y, 0.f),
                                        fmaxf(p1.x, 0.f), fmaxf(p1.y, 0.f));
        *(float4*)(c + 4) = make_float4(fmaxf(p2.x, 0.f), fmaxf(p2.y, 0.f),
                                        fmaxf(p3.x, 0.f), fmaxf(p3.y, 0.f));
    }
}

// ---------------------------------------------------------------------------
// K3: out = g_H @ W2[:, :64] + b2[:64], scattered back to [B,S,768].
// M=98304, N=64, K=512. 128x64x8 tiles, 128 threads, 8x8 micro, f32x2.
// ---------------------------------------------------------------------------
__global__ __launch_bounds__(128) void mlp2(const float* __restrict__ W2,
                                            const float* __restrict__ b2,
                                            float* __restrict__ out) {
    __shared__ float As[8][128];
    __shared__ float Bs[8][64];
    const int tid = threadIdx.x;
    const int tx = tid & 7, ty = tid >> 3;
    const int row0 = blockIdx.x * 128;
    const float* Ap = g_H + (long)(row0 + tid) * MEMHID;
    const int bRow = tid >> 4, bCol = (tid & 15) * 4;
    const float* Bp = W2 + (long)bRow * 256 + bCol;

    u64 acc[8][4];
    #pragma unroll
    for (int i = 0; i < 8; ++i)
        #pragma unroll
        for (int j = 0; j < 4; ++j) acc[i][j] = 0ull;

    for (int kt = 0; kt < MEMHID; kt += 8) {
        float4 a0 = *(const float4*)(Ap + kt);
        float4 a1 = *(const float4*)(Ap + kt + 4);
        As[0][tid] = a0.x; As[1][tid] = a0.y; As[2][tid] = a0.z; As[3][tid] = a0.w;
        As[4][tid] = a1.x; As[5][tid] = a1.y; As[6][tid] = a1.z; As[7][tid] = a1.w;
        *(float4*)&Bs[bRow][bCol] = *(const float4*)(Bp + (long)kt * 256);
        __syncthreads();
        #pragma unroll
        for (int k = 0; k < 8; ++k) MICRO_STEP(As, Bs, k, ty, tx, acc)
        __syncthreads();
    }

    float bo[8];
    *(float4*)&bo[0] = *(const float4*)&b2[tx * 8];
    *(float4*)&bo[4] = *(const float4*)&b2[tx * 8 + 4];
    #pragma unroll
    for (int i = 0; i < 8; ++i) {
        const int rr = row0 + ty * 8 + i;
        const int t = rr / NHEADS, hh = rr % NHEADS;
        float* c = out + (long)t * HIDDEN + hh * HD + tx * 8;
        float2 p0 = unp2(acc[i][0]), p1 = unp2(acc[i][1]);
        float2 p2 = unp2(acc[i][2]), p3 = unp2(acc[i][3]);
        *(float4*)c       = make_float4(p0.x + bo[0], p0.y + bo[1],
                                        p1.x + bo[2], p1.y + bo[3]);
        *(float4*)(c + 4) = make_float4(p2.x + bo[4], p2.y + bo[5],
                                        p3.x + bo[6], p3.y + bo[7]);
    }
}

// ---------------------------------------------------------------------------
// launch
// ---------------------------------------------------------------------------
extern "C" void kernel_launch(void* const* d_in, const int* in_sizes, int n_in,
                              void* d_out, int out_size) {
    const float* X      = (const float*)d_in[0];
    const float* Wq     = (const float*)d_in[1];
    const float* coeffs = (const float*)d_in[2];
    const float* W1     = (const float*)d_in[3];
    const float* b1     = (const float*)d_in[4];
    const float* W2     = (const float*)d_in[5];
    const float* b2     = (const float*)d_in[6];
    float* out = (float*)d_out;

    prep_b1eff<<<1, MEMHID>>>(W1, b1, coeffs);

    dim3 g1(HIDDEN / 128, TOKENS / 128);          // 6 x 64
    qproj<<<g1, 256>>>(X, Wq);

    dim3 g2(MEMHID / 128, ROWS_TOT / 128);        // 4 x 768
    poly_mlp1<<<g2, 256>>>(W1, coeffs);

    mlp2<<<ROWS_TOT / 128, 128>>>(W2, b2, out);
}

// round 7
// speedup vs baseline: 1.6346x; 1.5855x over previous
#include <cuda_runtime.h>
#include <cuda_bf16.h>
#include <cstdint>

// ---------------------------------------------------------------------------
// AtlasAttention round 7: mma.sync (HMMA bf16) 3-pass-split GEMM pipeline.
// tcgen05 is unreachable (harness targets plain compute_103), so we drive the
// tensor pipe via arch-generic mma.sync.m16n8k16 + ldmatrix.
//   K1: Q = X @ Wq            (epilogue: poly-expand q -> P split bf16)
//   K2: H = relu(P@W1'+b1')   (epilogue: split H -> bf16 hi/lo)
//   K3: out = H @ W2[:,:64] + b2[:64]
// Split: A' = [A_hi, A_hi, A_lo], B' = [B_hi, B_lo, B_hi]  (err ~2^-18)
// ---------------------------------------------------------------------------

#define TOKENS   8192
#define NHEADS   12
#define ROWS_TOT (TOKENS * NHEADS)   // 98304

typedef __nv_bfloat16 bf16;

__device__ bf16  g_Xhi[TOKENS * 768], g_Xlo[TOKENS * 768];
__device__ bf16  g_Phi[ROWS_TOT * 192], g_Plo[ROWS_TOT * 192];
__device__ bf16  g_Hhi[ROWS_TOT * 512], g_Hlo[ROWS_TOT * 512];
__device__ bf16  g_WqT_hi[768 * 768], g_WqT_lo[768 * 768];
__device__ bf16  g_W1T_hi[512 * 192], g_W1T_lo[512 * 192];
__device__ bf16  g_W2T_hi[64 * 512],  g_W2T_lo[64 * 512];
__device__ float g_b1eff[512];

// ------------------------------- helpers -----------------------------------
__device__ __forceinline__ uint32_t smem_u32(const void* p) {
    uint32_t a;
    asm("{ .reg .u64 t; cvta.to.shared.u64 t, %1; cvt.u32.u64 %0, t; }"
        : "=r"(a) : "l"(p));
    return a;
}
__device__ __forceinline__ uint32_t swz(uint32_t o) { return o ^ ((o >> 3) & 0x70); }

__device__ __forceinline__ void ldsm4(uint32_t& r0, uint32_t& r1, uint32_t& r2,
                                      uint32_t& r3, uint32_t addr) {
    asm volatile("ldmatrix.sync.aligned.m8n8.x4.shared.b16 {%0,%1,%2,%3}, [%4];"
                 : "=r"(r0), "=r"(r1), "=r"(r2), "=r"(r3) : "r"(addr));
}
__device__ __forceinline__ void mma_bf16(float* d, uint32_t a0, uint32_t a1,
                                         uint32_t a2, uint32_t a3,
                                         uint32_t b0, uint32_t b1) {
    asm volatile(
        "mma.sync.aligned.m16n8k16.row.col.f32.bf16.bf16.f32 "
        "{%0,%1,%2,%3}, {%4,%5,%6,%7}, {%8,%9}, {%0,%1,%2,%3};"
        : "+f"(d[0]), "+f"(d[1]), "+f"(d[2]), "+f"(d[3])
        : "r"(a0), "r"(a1), "r"(a2), "r"(a3), "r"(b0), "r"(b1));
}
__device__ __forceinline__ bf16 f2hi(float v) { return __float2bfloat16(v); }
__device__ __forceinline__ bf16 f2lo(float v) {
    return __float2bfloat16(v - __bfloat162float(__float2bfloat16(v)));
}
__device__ __forceinline__ uint32_t pkbf2(bf16 a, bf16 b) {
    unsigned short x = *(unsigned short*)&a, y = *(unsigned short*)&b;
    return (uint32_t)x | ((uint32_t)y << 16);
}

// ------------------------------ prep kernels -------------------------------
__global__ void prep_b1eff(const float* __restrict__ W1,
                           const float* __restrict__ b1,
                           const float* __restrict__ coeffs) {
    int j = threadIdx.x;
    if (j < 512) {
        float s = 0.f;
        #pragma unroll 8
        for (int d = 0; d < 64; ++d) s += W1[d * 512 + j];
        g_b1eff[j] = b1[j] + coeffs[0] * s;
    }
}
// dst[n*K + k] = split(src[(koff+k)*ld + n])
__global__ void splitT(const float* __restrict__ src, bf16* __restrict__ dhi,
                       bf16* __restrict__ dlo, int N, int K, int koff, int ld) {
    int i = blockIdx.x * 256 + threadIdx.x;
    if (i >= N * K) return;
    int n = i / K, k = i % K;
    float v = src[(long)(koff + k) * ld + n];
    bf16 h = __float2bfloat16(v);
    dhi[i] = h;
    dlo[i] = __float2bfloat16(v - __bfloat162float(h));
}
__global__ void splitX(const float* __restrict__ X, int n) {
    int i = blockIdx.x * 256 + threadIdx.x;
    if (i >= n) return;
    float v = X[i];
    bf16 h = __float2bfloat16(v);
    g_Xhi[i] = h;
    g_Xlo[i] = __float2bfloat16(v - __bfloat162float(h));
}

// ------------------------------- GEMM kernel -------------------------------
// MODE 0: A=Xhi/lo [8192x768],  B=WqT,  epi: poly-split -> g_Phi/g_Plo
// MODE 1: A=Phi/lo [98304x192], B=W1T,  epi: bias+relu+split -> g_Hhi/g_Hlo
// MODE 2: A=Hhi/lo [98304x512], B=W2T,  epi: bias+scatter -> out fp32
template <int MODE, int NT, int KORIG>
__global__ __launch_bounds__(256) void hmma_gemm(const float* __restrict__ bias,
                                                 const float* __restrict__ coeffs,
                                                 float* __restrict__ outf) {
    constexpr int CPT = KORIG / 64;
    constexpr int NC = 3 * CPT;
    constexpr int WN8 = NT / 16;         // per-warp n8 tiles
    constexpr int BTPR = 256 / NT;       // threads per B row
    constexpr int BNUM = 8 / BTPR;       // 16B chunks per thread (B)

    __shared__ __align__(128) char Asm[128 * 128];
    __shared__ __align__(128) char Bsm[NT * 128];
    __shared__ float sbias[NT];

    const int tid = threadIdx.x;
    const int wid = tid >> 5, lane = tid & 31;
    const int wm = wid & 3, wn = wid >> 2;
    const int row0 = blockIdx.y * 128;
    const int col0 = blockIdx.x * NT;

    if (MODE != 0 && tid < NT) sbias[tid] = bias[col0 + tid];

    // loader setup
    const int arow = tid >> 1, aoct0 = (tid & 1) * 4;
    const bf16* Ah;
    const bf16* Al;
    if (MODE == 0)      { Ah = g_Xhi; Al = g_Xlo; }
    else if (MODE == 1) { Ah = g_Phi; Al = g_Plo; }
    else                { Ah = g_Hhi; Al = g_Hlo; }
    Ah += (long)(row0 + arow) * KORIG;
    Al += (long)(row0 + arow) * KORIG;

    const int brow = tid / BTPR, boct0 = (tid % BTPR) * BNUM;
    const bf16* Bh;
    const bf16* Bl;
    if (MODE == 0)      { Bh = g_WqT_hi; Bl = g_WqT_lo; }
    else if (MODE == 1) { Bh = g_W1T_hi; Bl = g_W1T_lo; }
    else                { Bh = g_W2T_hi; Bl = g_W2T_lo; }
    Bh += (long)(col0 + brow) * KORIG;
    Bl += (long)(col0 + brow) * KORIG;

    float acc[2][WN8][4];
    #pragma unroll
    for (int mi = 0; mi < 2; ++mi)
        #pragma unroll
        for (int nt = 0; nt < WN8; ++nt)
            #pragma unroll
            for (int j = 0; j < 4; ++j) acc[mi][nt][j] = 0.f;

    const uint32_t Ab = smem_u32(Asm), Bb = smem_u32(Bsm);

    uint4 araw[4], braw[BNUM];
    {   // prologue: chunk 0 (third 0: hi*hi)
        #pragma unroll
        for (int i = 0; i < 4; ++i)
            araw[i] = *(const uint4*)(Ah + (aoct0 + i) * 8);
        #pragma unroll
        for (int i = 0; i < BNUM; ++i)
            braw[i] = *(const uint4*)(Bh + (boct0 + i) * 8);
    }

    for (int c = 0; c < NC; ++c) {
        // store prefetched chunk c
        #pragma unroll
        for (int i = 0; i < 4; ++i)
            *(uint4*)(Asm + swz(arow * 128 + (aoct0 + i) * 16)) = araw[i];
        #pragma unroll
        for (int i = 0; i < BNUM; ++i)
            *(uint4*)(Bsm + swz(brow * 128 + (boct0 + i) * 16)) = braw[i];
        __syncthreads();

        if (c + 1 < NC) {   // issue gmem loads for chunk c+1 (overlap with mma)
            const int cn = c + 1;
            const int third = cn / CPT;
            const int kk = (cn % CPT) * 64;
            const bf16* a = (third == 2) ? Al : Ah;
            const bf16* b = (third == 1) ? Bl : Bh;
            #pragma unroll
            for (int i = 0; i < 4; ++i)
                araw[i] = *(const uint4*)(a + kk + (aoct0 + i) * 8);
            #pragma unroll
            for (int i = 0; i < BNUM; ++i)
                braw[i] = *(const uint4*)(b + kk + (boct0 + i) * 8);
        }

        // compute: 4 k16 steps over the 64-K chunk
        #pragma unroll
        for (int ks = 0; ks < 4; ++ks) {
            uint32_t af[2][4];
            #pragma unroll
            for (int mi = 0; mi < 2; ++mi) {
                const int r = wm * 32 + mi * 16 + (lane & 15);
                ldsm4(af[mi][0], af[mi][1], af[mi][2], af[mi][3],
                      Ab + swz(r * 128 + ks * 32 + (lane >> 4) * 16));
            }
            uint32_t bfr[WN8][2];
            #pragma unroll
            for (int g = 0; g < WN8 / 2; ++g) {
                const int nr = wn * (NT / 2) + g * 16 + (lane & 15);
                uint32_t r0, r1, r2, r3;
                ldsm4(r0, r1, r2, r3,
                      Bb + swz(nr * 128 + ks * 32 + (lane >> 4) * 16));
                bfr[2 * g][0] = r0; bfr[2 * g][1] = r2;
                bfr[2 * g + 1][0] = r1; bfr[2 * g + 1][1] = r3;
            }
            #pragma unroll
            for (int mi = 0; mi < 2; ++mi)
                #pragma unroll
                for (int nt = 0; nt < WN8; ++nt)
                    mma_bf16(acc[mi][nt], af[mi][0], af[mi][1], af[mi][2],
                             af[mi][3], bfr[nt][0], bfr[nt][1]);
        }
        __syncthreads();
    }

    // ------------------------------ epilogue -------------------------------
    float ca[3];
    if (MODE == 0) { ca[0] = coeffs[1]; ca[1] = coeffs[2]; ca[2] = coeffs[3]; }

    #pragma unroll
    for (int mi = 0; mi < 2; ++mi) {
        #pragma unroll
        for (int nt = 0; nt < WN8; ++nt) {
            const int cg = col0 + wn * (NT / 2) + nt * 8 + 2 * (lane & 3);
            #pragma unroll
            for (int h = 0; h < 2; ++h) {   // h=0: d0,d1 ; h=1: d2,d3
                const int r = row0 + wm * 32 + mi * 16 + (lane >> 2) + h * 8;
                float v0 = acc[mi][nt][2 * h];
                float v1 = acc[mi][nt][2 * h + 1];
                if (MODE == 0) {
                    // poly expand q -> P split
                    const int head = cg >> 6, d = cg & 63;
                    const long pb = (long)(r * NHEADS + head) * 192 + d;
                    float x0 = fminf(fmaxf(v0, -10.f), 10.f);
                    float x1 = fminf(fmaxf(v1, -10.f), 10.f);
                    float y0 = x0, y1 = x1;
                    #pragma unroll
                    for (int a = 0; a < 3; ++a) {
                        float f0 = fminf(fmaxf(ca[a] * y0, -1e6f), 1e6f);
                        float f1 = fminf(fmaxf(ca[a] * y1, -1e6f), 1e6f);
                        bf16 h0 = f2hi(f0), h1 = f2hi(f1);
                        *(uint32_t*)&g_Phi[pb + a * 64] = pkbf2(h0, h1);
                        *(uint32_t*)&g_Plo[pb + a * 64] = pkbf2(
                            __float2bfloat16(f0 - __bfloat162float(h0)),
                            __float2bfloat16(f1 - __bfloat162float(h1)));
                        y0 *= x0; y1 *= x1;
                    }
                } else if (MODE == 1) {
                    const int cl = cg - col0;
                    v0 = fmaxf(v0 + sbias[cl], 0.f);
                    v1 = fmaxf(v1 + sbias[cl + 1], 0.f);
                    bf16 h0 = f2hi(v0), h1 = f2hi(v1);
                    const long o = (long)r * 512 + cg;
                    *(uint32_t*)&g_Hhi[o] = pkbf2(h0, h1);
                    *(uint32_t*)&g_Hlo[o] = pkbf2(
                        __float2bfloat16(v0 - __bfloat162float(h0)),
                        __float2bfloat16(v1 - __bfloat162float(h1)));
                } else {
                    const int t = r / NHEADS, hh = r % NHEADS;
                    float2 v = make_float2(v0 + sbias[cg], v1 + sbias[cg + 1]);
                    *(float2*)&outf[(long)t * 768 + hh * 64 + cg] = v;
                }
            }
        }
    }
}

// --------------------------------- launch ----------------------------------
extern "C" void kernel_launch(void* const* d_in, const int* in_sizes, int n_in,
                              void* d_out, int out_size) {
    const float* X      = (const float*)d_in[0];
    const float* Wq     = (const float*)d_in[1];
    const float* coeffs = (const float*)d_in[2];
    const float* W1     = (const float*)d_in[3];
    const float* b1     = (const float*)d_in[4];
    const float* W2     = (const float*)d_in[5];
    const float* b2     = (const float*)d_in[6];
    float* out = (float*)d_out;

    bf16 *wqh, *wql, *w1h, *w1l, *w2h, *w2l;
    float* b1e;
    cudaGetSymbolAddress((void**)&wqh, g_WqT_hi);
    cudaGetSymbolAddress((void**)&wql, g_WqT_lo);
    cudaGetSymbolAddress((void**)&w1h, g_W1T_hi);
    cudaGetSymbolAddress((void**)&w1l, g_W1T_lo);
    cudaGetSymbolAddress((void**)&w2h, g_W2T_hi);
    cudaGetSymbolAddress((void**)&w2l, g_W2T_lo);
    cudaGetSymbolAddress((void**)&b1e, g_b1eff);

    prep_b1eff<<<1, 512>>>(W1, b1, coeffs);
    splitT<<<(768 * 768 + 255) / 256, 256>>>(Wq, wqh, wql, 768, 768, 0, 768);
    splitT<<<(512 * 192 + 255) / 256, 256>>>(W1, w1h, w1l, 512, 192, 64, 512);
    splitT<<<(64 * 512 + 255) / 256, 256>>>(W2, w2h, w2l, 64, 512, 0, 256);
    splitX<<<(TOKENS * 768 + 255) / 256, 256>>>(X, TOKENS * 768);

    dim3 g0(6, 64);     // N=768/128, M=8192/128
    hmma_gemm<0, 128, 768><<<g0, 256>>>(nullptr, coeffs, nullptr);

    dim3 g1(4, 768);    // N=512/128, M=98304/128
    hmma_gemm<1, 128, 192><<<g1, 256>>>(b1e, nullptr, nullptr);

    dim3 g2(1, 768);    // N=64, M=98304/128
    hmma_gemm<2, 64, 512><<<g2, 256>>>(b2, nullptr, out);
}

// round 8
// speedup vs baseline: 2.7929x; 1.7087x over previous
#include <cuda_runtime.h>
#include <cuda_bf16.h>
#include <cuda_fp16.h>
#include <cstdint>

// ---------------------------------------------------------------------------
// AtlasAttention round 8: HMMA pipeline with precision-tiered passes.
//   K1: Q = X @ Wq     bf16 3-pass split (poly amplifies error ~3x)
//       epilogue: poly-expand -> P fp16 single
//   K2: H = relu(P @ W1' + b1')  fp16 2-pass (W1 split, P single)
//   K3: out = H @ W2[:,:64]+b2   fp16 2-pass (W2 split, H single)
// cp.async 3-stage smem pipeline, one __syncthreads per 64-K chunk.
// ---------------------------------------------------------------------------

#define TOKENS   8192
#define NHEADS   12
#define ROWS_TOT (TOKENS * NHEADS)   // 98304

typedef __nv_bfloat16 bf16;
typedef __half fp16;
typedef uint16_t u16;

__device__ bf16 g_Xhi[TOKENS * 768], g_Xlo[TOKENS * 768];
__device__ bf16 g_WqT_hi[768 * 768], g_WqT_lo[768 * 768];
__device__ fp16 g_P[ROWS_TOT * 192];
__device__ fp16 g_W1T_hi[512 * 192], g_W1T_lo[512 * 192];
__device__ fp16 g_H[ROWS_TOT * 512];
__device__ fp16 g_W2T_hi[64 * 512],  g_W2T_lo[64 * 512];
__device__ float g_b1eff[512];

// ------------------------------- helpers -----------------------------------
__device__ __forceinline__ uint32_t smem_u32(const void* p) {
    uint32_t a;
    asm("{ .reg .u64 t; cvta.to.shared.u64 t, %1; cvt.u32.u64 %0, t; }"
        : "=r"(a) : "l"(p));
    return a;
}
__device__ __forceinline__ uint32_t swz(uint32_t o) { return o ^ ((o >> 3) & 0x70); }

__device__ __forceinline__ void ldsm4(uint32_t& r0, uint32_t& r1, uint32_t& r2,
                                      uint32_t& r3, uint32_t addr) {
    asm volatile("ldmatrix.sync.aligned.m8n8.x4.shared.b16 {%0,%1,%2,%3}, [%4];"
                 : "=r"(r0), "=r"(r1), "=r"(r2), "=r"(r3) : "r"(addr));
}
template <bool FP16MMA>
__device__ __forceinline__ void mma16816(float* d, uint32_t a0, uint32_t a1,
                                         uint32_t a2, uint32_t a3,
                                         uint32_t b0, uint32_t b1) {
    if (FP16MMA)
        asm volatile(
            "mma.sync.aligned.m16n8k16.row.col.f32.f16.f16.f32 "
            "{%0,%1,%2,%3}, {%4,%5,%6,%7}, {%8,%9}, {%0,%1,%2,%3};"
            : "+f"(d[0]), "+f"(d[1]), "+f"(d[2]), "+f"(d[3])
            : "r"(a0), "r"(a1), "r"(a2), "r"(a3), "r"(b0), "r"(b1));
    else
        asm volatile(
            "mma.sync.aligned.m16n8k16.row.col.f32.bf16.bf16.f32 "
            "{%0,%1,%2,%3}, {%4,%5,%6,%7}, {%8,%9}, {%0,%1,%2,%3};"
            : "+f"(d[0]), "+f"(d[1]), "+f"(d[2]), "+f"(d[3])
            : "r"(a0), "r"(a1), "r"(a2), "r"(a3), "r"(b0), "r"(b1));
}
__device__ __forceinline__ void cp16(uint32_t dst, const void* src) {
    asm volatile("cp.async.cg.shared.global [%0], [%1], 16;"
                 :: "r"(dst), "l"(src));
}
#define CP_COMMIT() asm volatile("cp.async.commit_group;" ::: "memory")
#define CP_WAIT1()  asm volatile("cp.async.wait_group 1;" ::: "memory")
#define CP_WAIT0()  asm volatile("cp.async.wait_group 0;" ::: "memory")

__device__ __forceinline__ bf16 b2hi(float v) { return __float2bfloat16(v); }

// ------------------------------ prep kernels -------------------------------
__global__ void prep_b1eff(const float* __restrict__ W1,
                           const float* __restrict__ b1,
                           const float* __restrict__ coeffs) {
    int j = threadIdx.x;
    if (j < 512) {
        float s = 0.f;
        #pragma unroll 8
        for (int d = 0; d < 64; ++d) s += W1[d * 512 + j];
        g_b1eff[j] = b1[j] + coeffs[0] * s;
    }
}
// bf16 split transpose: dst[n*K + k] = split(src[(koff+k)*ld + n])
__global__ void splitT_bf(const float* __restrict__ src, bf16* __restrict__ dhi,
                          bf16* __restrict__ dlo, int N, int K, int koff, int ld) {
    int i = blockIdx.x * 256 + threadIdx.x;
    if (i >= N * K) return;
    int n = i / K, k = i % K;
    float v = src[(long)(koff + k) * ld + n];
    bf16 h = __float2bfloat16(v);
    dhi[i] = h;
    dlo[i] = __float2bfloat16(v - __bfloat162float(h));
}
// fp16 split transpose
__global__ void splitT_h(const float* __restrict__ src, fp16* __restrict__ dhi,
                         fp16* __restrict__ dlo, int N, int K, int koff, int ld) {
    int i = blockIdx.x * 256 + threadIdx.x;
    if (i >= N * K) return;
    int n = i / K, k = i % K;
    float v = src[(long)(koff + k) * ld + n];
    fp16 h = __float2half_rn(v);
    dhi[i] = h;
    dlo[i] = __float2half_rn(v - __half2float(h));
}
__global__ void splitX(const float* __restrict__ X, int n) {
    int i = blockIdx.x * 256 + threadIdx.x;
    if (i >= n) return;
    float v = X[i];
    bf16 h = __float2bfloat16(v);
    g_Xhi[i] = h;
    g_Xlo[i] = __float2bfloat16(v - __bfloat162float(h));
}

// ------------------------------- GEMM kernel -------------------------------
// MODE 0: A=Xhi/lo bf16 [8192x768]  B=WqT bf16 split   epi: poly -> g_P fp16
// MODE 1: A=g_P fp16 [98304x192]    B=W1T fp16 split   epi: bias+relu -> g_H
// MODE 2: A=g_H fp16 [98304x512]    B=W2T fp16 split   epi: bias+scatter
template <int MODE, int NT, int KORIG, int PASSES, bool FP16MMA>
__global__ __launch_bounds__(256, 2) void hmma_gemm(const float* __restrict__ bias,
                                                    const float* __restrict__ coeffs,
                                                    float* __restrict__ outf) {
    constexpr int CPT = KORIG / 64;
    constexpr int NC = PASSES * CPT;
    constexpr int ASZ = 128 * 128;       // bytes per A stage
    constexpr int BSZ = NT * 128;
    constexpr int STG = ASZ + BSZ;
    constexpr int WN8 = NT / 16;
    constexpr int BTPR = 256 / NT;
    constexpr int BNUM = 8 / BTPR;

    extern __shared__ char sm[];
    __shared__ float sbias[NT];

    const int tid = threadIdx.x;
    const int wid = tid >> 5, lane = tid & 31;
    const int wm = wid & 3, wn = wid >> 2;
    const int row0 = blockIdx.y * 128;
    const int col0 = blockIdx.x * NT;
    const uint32_t smb = smem_u32(sm);

    // loader setup
    const int arow = tid >> 1, aoct0 = (tid & 1) * 4;
    const int brow = tid / BTPR, boct0 = (tid % BTPR) * BNUM;
    const u16 *Ah, *Al, *Bh, *Bl;
    if (MODE == 0) {
        Ah = (const u16*)g_Xhi; Al = (const u16*)g_Xlo;
        Bh = (const u16*)g_WqT_hi; Bl = (const u16*)g_WqT_lo;
    } else if (MODE == 1) {
        Ah = (const u16*)g_P; Al = Ah;
        Bh = (const u16*)g_W1T_hi; Bl = (const u16*)g_W1T_lo;
    } else {
        Ah = (const u16*)g_H; Al = Ah;
        Bh = (const u16*)g_W2T_hi; Bl = (const u16*)g_W2T_lo;
    }
    Ah += (long)(row0 + arow) * KORIG;
    Al += (long)(row0 + arow) * KORIG;
    Bh += (long)(col0 + brow) * KORIG;
    Bl += (long)(col0 + brow) * KORIG;

    auto issue = [&](int c) {
        const int s = c % 3;
        const int third = c / CPT;
        const int kk = (c % CPT) * 64;
        const u16* a = (PASSES == 3 && third == 2) ? Al : Ah;
        const u16* b = (third == 1) ? Bl : Bh;
        const uint32_t Ab = smb + s * STG;
        const uint32_t Bb = Ab + ASZ;
        #pragma unroll
        for (int i = 0; i < 4; ++i)
            cp16(Ab + swz(arow * 128 + (aoct0 + i) * 16), a + kk + (aoct0 + i) * 8);
        #pragma unroll
        for (int i = 0; i < BNUM; ++i)
            cp16(Bb + swz(brow * 128 + (boct0 + i) * 16), b + kk + (boct0 + i) * 8);
        CP_COMMIT();
    };

    issue(0);
    issue(1);
    if (MODE != 0 && tid < NT) sbias[tid] = bias[col0 + tid];

    float acc[2][WN8][4];
    #pragma unroll
    for (int mi = 0; mi < 2; ++mi)
        #pragma unroll
        for (int nt = 0; nt < WN8; ++nt)
            #pragma unroll
            for (int j = 0; j < 4; ++j) acc[mi][nt][j] = 0.f;

    for (int c = 0; c < NC; ++c) {
        if (c + 1 < NC) CP_WAIT1(); else CP_WAIT0();
        __syncthreads();
        if (c + 2 < NC) issue(c + 2);

        const int s = c % 3;
        const uint32_t Ab = smb + s * STG;
        const uint32_t Bb = Ab + ASZ;
        #pragma unroll
        for (int ks = 0; ks < 4; ++ks) {
            uint32_t af[2][4];
            #pragma unroll
            for (int mi = 0; mi < 2; ++mi) {
                const int r = wm * 32 + mi * 16 + (lane & 15);
                ldsm4(af[mi][0], af[mi][1], af[mi][2], af[mi][3],
                      Ab + swz(r * 128 + ks * 32 + (lane >> 4) * 16));
            }
            uint32_t bfr[WN8][2];
            #pragma unroll
            for (int g = 0; g < WN8 / 2; ++g) {
                const int nr = wn * (NT / 2) + g * 16 + (lane & 15);
                uint32_t r0, r1, r2, r3;
                ldsm4(r0, r1, r2, r3,
                      Bb + swz(nr * 128 + ks * 32 + (lane >> 4) * 16));
                bfr[2 * g][0] = r0; bfr[2 * g][1] = r2;
                bfr[2 * g + 1][0] = r1; bfr[2 * g + 1][1] = r3;
            }
            #pragma unroll
            for (int mi = 0; mi < 2; ++mi)
                #pragma unroll
                for (int nt = 0; nt < WN8; ++nt)
                    mma16816<FP16MMA>(acc[mi][nt], af[mi][0], af[mi][1],
                                      af[mi][2], af[mi][3],
                                      bfr[nt][0], bfr[nt][1]);
        }
    }

    // ------------------------------ epilogue -------------------------------
    float ca[3];
    if (MODE == 0) { ca[0] = coeffs[1]; ca[1] = coeffs[2]; ca[2] = coeffs[3]; }

    #pragma unroll
    for (int mi = 0; mi < 2; ++mi) {
        #pragma unroll
        for (int nt = 0; nt < WN8; ++nt) {
            const int cg = col0 + wn * (NT / 2) + nt * 8 + 2 * (lane & 3);
            #pragma unroll
            for (int h = 0; h < 2; ++h) {
                const int r = row0 + wm * 32 + mi * 16 + (lane >> 2) + h * 8;
                float v0 = acc[mi][nt][2 * h];
                float v1 = acc[mi][nt][2 * h + 1];
                if (MODE == 0) {
                    const int head = cg >> 6, d = cg & 63;
                    const long pb = (long)(r * NHEADS + head) * 192 + d;
                    float x0 = fminf(fmaxf(v0, -10.f), 10.f);
                    float x1 = fminf(fmaxf(v1, -10.f), 10.f);
                    float y0 = x0, y1 = x1;
                    #pragma unroll
                    for (int a = 0; a < 3; ++a) {
                        float f0 = fminf(fmaxf(ca[a] * y0, -1e6f), 1e6f);
                        float f1 = fminf(fmaxf(ca[a] * y1, -1e6f), 1e6f);
                        *(__half2*)&g_P[pb + a * 64] = __floats2half2_rn(f0, f1);
                        y0 *= x0; y1 *= x1;
                    }
                } else if (MODE == 1) {
                    const int cl = cg - col0;
                    v0 = fmaxf(v0 + sbias[cl], 0.f);
                    v1 = fmaxf(v1 + sbias[cl + 1], 0.f);
                    *(__half2*)&g_H[(long)r * 512 + cg] = __floats2half2_rn(v0, v1);
                } else {
                    const int t = r / NHEADS, hh = r % NHEADS;
                    float2 v = make_float2(v0 + sbias[cg], v1 + sbias[cg + 1]);
                    *(float2*)&outf[(long)t * 768 + hh * 64 + cg] = v;
                }
            }
        }
    }
}

// --------------------------------- launch ----------------------------------
extern "C" void kernel_launch(void* const* d_in, const int* in_sizes, int n_in,
                              void* d_out, int out_size) {
    const float* X      = (const float*)d_in[0];
    const float* Wq     = (const float*)d_in[1];
    const float* coeffs = (const float*)d_in[2];
    const float* W1     = (const float*)d_in[3];
    const float* b1     = (const float*)d_in[4];
    const float* W2     = (const float*)d_in[5];
    const float* b2     = (const float*)d_in[6];
    float* out = (float*)d_out;

    bf16 *wqh, *wql;
    fp16 *w1h, *w1l, *w2h, *w2l;
    float* b1e;
    cudaGetSymbolAddress((void**)&wqh, g_WqT_hi);
    cudaGetSymbolAddress((void**)&wql, g_WqT_lo);
    cudaGetSymbolAddress((void**)&w1h, g_W1T_hi);
    cudaGetSymbolAddress((void**)&w1l, g_W1T_lo);
    cudaGetSymbolAddress((void**)&w2h, g_W2T_hi);
    cudaGetSymbolAddress((void**)&w2l, g_W2T_lo);
    cudaGetSymbolAddress((void**)&b1e, g_b1eff);

    prep_b1eff<<<1, 512>>>(W1, b1, coeffs);
    splitT_bf<<<(768 * 768 + 255) / 256, 256>>>(Wq, wqh, wql, 768, 768, 0, 768);
    splitT_h<<<(512 * 192 + 255) / 256, 256>>>(W1, w1h, w1l, 512, 192, 64, 512);
    splitT_h<<<(64 * 512 + 255) / 256, 256>>>(W2, w2h, w2l, 64, 512, 0, 256);
    splitX<<<(TOKENS * 768 + 255) / 256, 256>>>(X, TOKENS * 768);

    const int smem128 = 3 * (128 * 128 + 128 * 128);   // 98304
    const int smem64  = 3 * (128 * 128 + 64 * 128);    // 73728
    cudaFuncSetAttribute((const void*)hmma_gemm<0, 128, 768, 3, false>,
                         cudaFuncAttributeMaxDynamicSharedMemorySize, smem128);
    cudaFuncSetAttribute((const void*)hmma_gemm<1, 128, 192, 2, true>,
                         cudaFuncAttributeMaxDynamicSharedMemorySize, smem128);
    cudaFuncSetAttribute((const void*)hmma_gemm<2, 64, 512, 2, true>,
                         cudaFuncAttributeMaxDynamicSharedMemorySize, smem64);

    dim3 g0(6, 64);     // N=768/128, M=8192/128
    hmma_gemm<0, 128, 768, 3, false><<<g0, 256, smem128>>>(nullptr, coeffs, nullptr);

    dim3 g1(4, 768);    // N=512/128, M=98304/128
    hmma_gemm<1, 128, 192, 2, true><<<g1, 256, smem128>>>(b1e, nullptr, nullptr);

    dim3 g2(1, 768);    // N=64, M=98304/128
    hmma_gemm<2, 64, 512, 2, true><<<g2, 256, smem64>>>(b2, nullptr, out);
}

// round 9
// speedup vs baseline: 3.7660x; 1.3484x over previous
#include <cuda_runtime.h>
#include <cuda_bf16.h>
#include <cuda_fp16.h>
#include <cstdint>

// ---------------------------------------------------------------------------
// AtlasAttention round 9: HMMA pipeline, precision-tiered passes v2.
//   K1: Q = X @ Wq        bf16 3-pass split (poly amplifies q error ~3x)
//       epilogue: poly-expand -> P fp16 single
//   K2: H = relu(P @ W1' + b1')   fp16 SINGLE pass (W1 rounded once)
//   K3: out = H @ W2[:,:64]+b2    fp16 SINGLE pass (W2 rounded once)
// cp.async 3-stage smem pipeline, one __syncthreads per 64-K chunk.
// ---------------------------------------------------------------------------

#define TOKENS   8192
#define NHEADS   12
#define ROWS_TOT (TOKENS * NHEADS)   // 98304

typedef __nv_bfloat16 bf16;
typedef __half fp16;
typedef uint16_t u16;

__device__ bf16 g_Xhi[TOKENS * 768], g_Xlo[TOKENS * 768];
__device__ bf16 g_WqT_hi[768 * 768], g_WqT_lo[768 * 768];
__device__ fp16 g_P[ROWS_TOT * 192];
__device__ fp16 g_W1T[512 * 192];
__device__ fp16 g_H[ROWS_TOT * 512];
__device__ fp16 g_W2T[64 * 512];
__device__ float g_b1eff[512];

// ------------------------------- helpers -----------------------------------
__device__ __forceinline__ uint32_t smem_u32(const void* p) {
    uint32_t a;
    asm("{ .reg .u64 t; cvta.to.shared.u64 t, %1; cvt.u32.u64 %0, t; }"
        : "=r"(a) : "l"(p));
    return a;
}
__device__ __forceinline__ uint32_t swz(uint32_t o) { return o ^ ((o >> 3) & 0x70); }

__device__ __forceinline__ void ldsm4(uint32_t& r0, uint32_t& r1, uint32_t& r2,
                                      uint32_t& r3, uint32_t addr) {
    asm volatile("ldmatrix.sync.aligned.m8n8.x4.shared.b16 {%0,%1,%2,%3}, [%4];"
                 : "=r"(r0), "=r"(r1), "=r"(r2), "=r"(r3) : "r"(addr));
}
template <bool FP16MMA>
__device__ __forceinline__ void mma16816(float* d, uint32_t a0, uint32_t a1,
                                         uint32_t a2, uint32_t a3,
                                         uint32_t b0, uint32_t b1) {
    if (FP16MMA)
        asm volatile(
            "mma.sync.aligned.m16n8k16.row.col.f32.f16.f16.f32 "
            "{%0,%1,%2,%3}, {%4,%5,%6,%7}, {%8,%9}, {%0,%1,%2,%3};"
            : "+f"(d[0]), "+f"(d[1]), "+f"(d[2]), "+f"(d[3])
            : "r"(a0), "r"(a1), "r"(a2), "r"(a3), "r"(b0), "r"(b1));
    else
        asm volatile(
            "mma.sync.aligned.m16n8k16.row.col.f32.bf16.bf16.f32 "
            "{%0,%1,%2,%3}, {%4,%5,%6,%7}, {%8,%9}, {%0,%1,%2,%3};"
            : "+f"(d[0]), "+f"(d[1]), "+f"(d[2]), "+f"(d[3])
            : "r"(a0), "r"(a1), "r"(a2), "r"(a3), "r"(b0), "r"(b1));
}
__device__ __forceinline__ void cp16(uint32_t dst, const void* src) {
    asm volatile("cp.async.cg.shared.global [%0], [%1], 16;"
                 :: "r"(dst), "l"(src));
}
#define CP_COMMIT() asm volatile("cp.async.commit_group;" ::: "memory")
#define CP_WAIT1()  asm volatile("cp.async.wait_group 1;" ::: "memory")
#define CP_WAIT0()  asm volatile("cp.async.wait_group 0;" ::: "memory")

// ------------------------------ prep kernels -------------------------------
__global__ void prep_b1eff(const float* __restrict__ W1,
                           const float* __restrict__ b1,
                           const float* __restrict__ coeffs) {
    int j = threadIdx.x;
    if (j < 512) {
        float s = 0.f;
        #pragma unroll 8
        for (int d = 0; d < 64; ++d) s += W1[d * 512 + j];
        g_b1eff[j] = b1[j] + coeffs[0] * s;
    }
}
// bf16 split transpose: dst[n*K + k] = split(src[(koff+k)*ld + n])
__global__ void splitT_bf(const float* __restrict__ src, bf16* __restrict__ dhi,
                          bf16* __restrict__ dlo, int N, int K, int koff, int ld) {
    int i = blockIdx.x * 256 + threadIdx.x;
    if (i >= N * K) return;
    int n = i / K, k = i % K;
    float v = src[(long)(koff + k) * ld + n];
    bf16 h = __float2bfloat16(v);
    dhi[i] = h;
    dlo[i] = __float2bfloat16(v - __bfloat162float(h));
}
// fp16 cast transpose (single precision tier)
__global__ void castT_h(const float* __restrict__ src, fp16* __restrict__ dst,
                        int N, int K, int koff, int ld) {
    int i = blockIdx.x * 256 + threadIdx.x;
    if (i >= N * K) return;
    int n = i / K, k = i % K;
    dst[i] = __float2half_rn(src[(long)(koff + k) * ld + n]);
}
__global__ void splitX(const float* __restrict__ X, int n) {
    int i = blockIdx.x * 256 + threadIdx.x;
    if (i >= n) return;
    float v = X[i];
    bf16 h = __float2bfloat16(v);
    g_Xhi[i] = h;
    g_Xlo[i] = __float2bfloat16(v - __bfloat162float(h));
}

// ------------------------------- GEMM kernel -------------------------------
// MODE 0: A=Xhi/lo bf16 [8192x768]  B=WqT bf16 split  PASSES=3  epi: poly->g_P
// MODE 1: A=g_P fp16 [98304x192]    B=W1T fp16        PASSES=1  epi: relu->g_H
// MODE 2: A=g_H fp16 [98304x512]    B=W2T fp16        PASSES=1  epi: scatter
template <int MODE, int NT, int KORIG, int PASSES, bool FP16MMA>
__global__ __launch_bounds__(256, 2) void hmma_gemm(const float* __restrict__ bias,
                                                    const float* __restrict__ coeffs,
                                                    float* __restrict__ outf) {
    constexpr int CPT = KORIG / 64;
    constexpr int NC = PASSES * CPT;
    constexpr int ASZ = 128 * 128;       // bytes per A stage
    constexpr int BSZ = NT * 128;
    constexpr int STG = ASZ + BSZ;
    constexpr int WN8 = NT / 16;
    constexpr int BTPR = 256 / NT;
    constexpr int BNUM = 8 / BTPR;

    extern __shared__ char sm[];
    __shared__ float sbias[NT];

    const int tid = threadIdx.x;
    const int wid = tid >> 5, lane = tid & 31;
    const int wm = wid & 3, wn = wid >> 2;
    const int row0 = blockIdx.y * 128;
    const int col0 = blockIdx.x * NT;
    const uint32_t smb = smem_u32(sm);

    // loader setup
    const int arow = tid >> 1, aoct0 = (tid & 1) * 4;
    const int brow = tid / BTPR, boct0 = (tid % BTPR) * BNUM;
    const u16 *Ah, *Al, *Bh, *Bl;
    if (MODE == 0) {
        Ah = (const u16*)g_Xhi; Al = (const u16*)g_Xlo;
        Bh = (const u16*)g_WqT_hi; Bl = (const u16*)g_WqT_lo;
    } else if (MODE == 1) {
        Ah = (const u16*)g_P; Al = Ah;
        Bh = (const u16*)g_W1T; Bl = Bh;
    } else {
        Ah = (const u16*)g_H; Al = Ah;
        Bh = (const u16*)g_W2T; Bl = Bh;
    }
    Ah += (long)(row0 + arow) * KORIG;
    Al += (long)(row0 + arow) * KORIG;
    Bh += (long)(col0 + brow) * KORIG;
    Bl += (long)(col0 + brow) * KORIG;

    auto issue = [&](int c) {
        const int s = c % 3;
        const int third = c / CPT;
        const int kk = (c % CPT) * 64;
        const u16* a = (PASSES == 3 && third == 2) ? Al : Ah;
        const u16* b = (PASSES == 3 && third == 1) ? Bl : Bh;
        const uint32_t Ab = smb + s * STG;
        const uint32_t Bb = Ab + ASZ;
        #pragma unroll
        for (int i = 0; i < 4; ++i)
            cp16(Ab + swz(arow * 128 + (aoct0 + i) * 16), a + kk + (aoct0 + i) * 8);
        #pragma unroll
        for (int i = 0; i < BNUM; ++i)
            cp16(Bb + swz(brow * 128 + (boct0 + i) * 16), b + kk + (boct0 + i) * 8);
        CP_COMMIT();
    };

    issue(0);
    issue(1);
    if (MODE != 0 && tid < NT) sbias[tid] = bias[col0 + tid];

    float acc[2][WN8][4];
    #pragma unroll
    for (int mi = 0; mi < 2; ++mi)
        #pragma unroll
        for (int nt = 0; nt < WN8; ++nt)
            #pragma unroll
            for (int j = 0; j < 4; ++j) acc[mi][nt][j] = 0.f;

    for (int c = 0; c < NC; ++c) {
        if (c + 1 < NC) CP_WAIT1(); else CP_WAIT0();
        __syncthreads();
        if (c + 2 < NC) issue(c + 2);

        const int s = c % 3;
        const uint32_t Ab = smb + s * STG;
        const uint32_t Bb = Ab + ASZ;
        #pragma unroll
        for (int ks = 0; ks < 4; ++ks) {
            uint32_t af[2][4];
            #pragma unroll
            for (int mi = 0; mi < 2; ++mi) {
                const int r = wm * 32 + mi * 16 + (lane & 15);
                ldsm4(af[mi][0], af[mi][1], af[mi][2], af[mi][3],
                      Ab + swz(r * 128 + ks * 32 + (lane >> 4) * 16));
            }
            uint32_t bfr[WN8][2];
            #pragma unroll
            for (int g = 0; g < WN8 / 2; ++g) {
                const int nr = wn * (NT / 2) + g * 16 + (lane & 15);
                uint32_t r0, r1, r2, r3;
                ldsm4(r0, r1, r2, r3,
                      Bb + swz(nr * 128 + ks * 32 + (lane >> 4) * 16));
                bfr[2 * g][0] = r0; bfr[2 * g][1] = r2;
                bfr[2 * g + 1][0] = r1; bfr[2 * g + 1][1] = r3;
            }
            #pragma unroll
            for (int mi = 0; mi < 2; ++mi)
                #pragma unroll
                for (int nt = 0; nt < WN8; ++nt)
                    mma16816<FP16MMA>(acc[mi][nt], af[mi][0], af[mi][1],
                                      af[mi][2], af[mi][3],
                                      bfr[nt][0], bfr[nt][1]);
        }
    }

    // ------------------------------ epilogue -------------------------------
    float ca[3];
    if (MODE == 0) { ca[0] = coeffs[1]; ca[1] = coeffs[2]; ca[2] = coeffs[3]; }

    #pragma unroll
    for (int mi = 0; mi < 2; ++mi) {
        #pragma unroll
        for (int nt = 0; nt < WN8; ++nt) {
            const int cg = col0 + wn * (NT / 2) + nt * 8 + 2 * (lane & 3);
            #pragma unroll
            for (int h = 0; h < 2; ++h) {
                const int r = row0 + wm * 32 + mi * 16 + (lane >> 2) + h * 8;
                float v0 = acc[mi][nt][2 * h];
                float v1 = acc[mi][nt][2 * h + 1];
                if (MODE == 0) {
                    const int head = cg >> 6, d = cg & 63;
                    const long pb = (long)(r * NHEADS + head) * 192 + d;
                    float x0 = fminf(fmaxf(v0, -10.f), 10.f);
                    float x1 = fminf(fmaxf(v1, -10.f), 10.f);
                    float y0 = x0, y1 = x1;
                    #pragma unroll
                    for (int a = 0; a < 3; ++a) {
                        float f0 = fminf(fmaxf(ca[a] * y0, -1e6f), 1e6f);
                        float f1 = fminf(fmaxf(ca[a] * y1, -1e6f), 1e6f);
                        *(__half2*)&g_P[pb + a * 64] = __floats2half2_rn(f0, f1);
                        y0 *= x0; y1 *= x1;
                    }
                } else if (MODE == 1) {
                    const int cl = cg - col0;
                    v0 = fmaxf(v0 + sbias[cl], 0.f);
                    v1 = fmaxf(v1 + sbias[cl + 1], 0.f);
                    *(__half2*)&g_H[(long)r * 512 + cg] = __floats2half2_rn(v0, v1);
                } else {
                    const int t = r / NHEADS, hh = r % NHEADS;
                    float2 v = make_float2(v0 + sbias[cg], v1 + sbias[cg + 1]);
                    *(float2*)&outf[(long)t * 768 + hh * 64 + cg] = v;
                }
            }
        }
    }
}

// --------------------------------- launch ----------------------------------
extern "C" void kernel_launch(void* const* d_in, const int* in_sizes, int n_in,
                              void* d_out, int out_size) {
    const float* X      = (const float*)d_in[0];
    const float* Wq     = (const float*)d_in[1];
    const float* coeffs = (const float*)d_in[2];
    const float* W1     = (const float*)d_in[3];
    const float* b1     = (const float*)d_in[4];
    const float* W2     = (const float*)d_in[5];
    const float* b2     = (const float*)d_in[6];
    float* out = (float*)d_out;

    bf16 *wqh, *wql;
    fp16 *w1t, *w2t;
    float* b1e;
    cudaGetSymbolAddress((void**)&wqh, g_WqT_hi);
    cudaGetSymbolAddress((void**)&wql, g_WqT_lo);
    cudaGetSymbolAddress((void**)&w1t, g_W1T);
    cudaGetSymbolAddress((void**)&w2t, g_W2T);
    cudaGetSymbolAddress((void**)&b1e, g_b1eff);

    prep_b1eff<<<1, 512>>>(W1, b1, coeffs);
    splitT_bf<<<(768 * 768 + 255) / 256, 256>>>(Wq, wqh, wql, 768, 768, 0, 768);
    castT_h<<<(512 * 192 + 255) / 256, 256>>>(W1, w1t, 512, 192, 64, 512);
    castT_h<<<(64 * 512 + 255) / 256, 256>>>(W2, w2t, 64, 512, 0, 256);
    splitX<<<(TOKENS * 768 + 255) / 256, 256>>>(X, TOKENS * 768);

    const int smem128 = 3 * (128 * 128 + 128 * 128);   // 98304
    const int smem64  = 3 * (128 * 128 + 64 * 128);    // 73728
    cudaFuncSetAttribute((const void*)hmma_gemm<0, 128, 768, 3, false>,
                         cudaFuncAttributeMaxDynamicSharedMemorySize, smem128);
    cudaFuncSetAttribute((const void*)hmma_gemm<1, 128, 192, 1, true>,
                         cudaFuncAttributeMaxDynamicSharedMemorySize, smem128);
    cudaFuncSetAttribute((const void*)hmma_gemm<2, 64, 512, 1, true>,
                         cudaFuncAttributeMaxDynamicSharedMemorySize, smem64);

    dim3 g0(6, 64);     // N=768/128, M=8192/128
    hmma_gemm<0, 128, 768, 3, false><<<g0, 256, smem128>>>(nullptr, coeffs, nullptr);

    dim3 g1(4, 768);    // N=512/128, M=98304/128
    hmma_gemm<1, 128, 192, 1, true><<<g1, 256, smem128>>>(b1e, nullptr, nullptr);

    dim3 g2(1, 768);    // N=64, M=98304/128
    hmma_gemm<2, 64, 512, 1, true><<<g2, 256, smem64>>>(b2, nullptr, out);
}

// round 10
// speedup vs baseline: 3.8595x; 1.0248x over previous
#include <cuda_runtime.h>
#include <cuda_bf16.h>
#include <cuda_fp16.h>
#include <cstdint>

// ---------------------------------------------------------------------------
// AtlasAttention round 10: HMMA pipeline, K2+K3 fused (H never leaves smem).
//   K1 (qproj): Q = X @ Wq, bf16 3-pass split; epilogue poly-expand -> g_P fp16
//   K23 (fused_mlp): per 128-row CTA:
//       P tile resident in smem; for each 128-wide hidden chunk:
//         GEMM1 (K=192) -> relu -> Hs smem fp16 -> GEMM2 (out 64 cols, fp32 acc)
// ---------------------------------------------------------------------------

#define TOKENS   8192
#define NHEADS   12
#define ROWS_TOT (TOKENS * NHEADS)   // 98304

typedef __nv_bfloat16 bf16;
typedef __half fp16;
typedef uint16_t u16;

__device__ bf16 g_Xhi[TOKENS * 768], g_Xlo[TOKENS * 768];
__device__ bf16 g_WqT_hi[768 * 768], g_WqT_lo[768 * 768];
__device__ fp16 g_P[ROWS_TOT * 192];
__device__ fp16 g_W1T[512 * 192];          // [n, k] n<512 hidden, k<192 poly
__device__ fp16 g_W2T[64 * 512];           // [n, k] n<64 out, k<512 hidden
__device__ float g_b1eff[512];

// ------------------------------- helpers -----------------------------------
__device__ __forceinline__ uint32_t smem_u32(const void* p) {
    uint32_t a;
    asm("{ .reg .u64 t; cvta.to.shared.u64 t, %1; cvt.u32.u64 %0, t; }"
        : "=r"(a) : "l"(p));
    return a;
}
__device__ __forceinline__ uint32_t swz(uint32_t o) { return o ^ ((o >> 3) & 0x70); }

__device__ __forceinline__ void ldsm4(uint32_t& r0, uint32_t& r1, uint32_t& r2,
                                      uint32_t& r3, uint32_t addr) {
    asm volatile("ldmatrix.sync.aligned.m8n8.x4.shared.b16 {%0,%1,%2,%3}, [%4];"
                 : "=r"(r0), "=r"(r1), "=r"(r2), "=r"(r3) : "r"(addr));
}
__device__ __forceinline__ void mma_f16(float* d, uint32_t a0, uint32_t a1,
                                        uint32_t a2, uint32_t a3,
                                        uint32_t b0, uint32_t b1) {
    asm volatile(
        "mma.sync.aligned.m16n8k16.row.col.f32.f16.f16.f32 "
        "{%0,%1,%2,%3}, {%4,%5,%6,%7}, {%8,%9}, {%0,%1,%2,%3};"
        : "+f"(d[0]), "+f"(d[1]), "+f"(d[2]), "+f"(d[3])
        : "r"(a0), "r"(a1), "r"(a2), "r"(a3), "r"(b0), "r"(b1));
}
__device__ __forceinline__ void mma_bf16(float* d, uint32_t a0, uint32_t a1,
                                         uint32_t a2, uint32_t a3,
                                         uint32_t b0, uint32_t b1) {
    asm volatile(
        "mma.sync.aligned.m16n8k16.row.col.f32.bf16.bf16.f32 "
        "{%0,%1,%2,%3}, {%4,%5,%6,%7}, {%8,%9}, {%0,%1,%2,%3};"
        : "+f"(d[0]), "+f"(d[1]), "+f"(d[2]), "+f"(d[3])
        : "r"(a0), "r"(a1), "r"(a2), "r"(a3), "r"(b0), "r"(b1));
}
__device__ __forceinline__ void cp16(uint32_t dst, const void* src) {
    asm volatile("cp.async.cg.shared.global [%0], [%1], 16;"
                 :: "r"(dst), "l"(src));
}
#define CP_COMMIT() asm volatile("cp.async.commit_group;" ::: "memory")
#define CP_WAIT1()  asm volatile("cp.async.wait_group 1;" ::: "memory")
#define CP_WAIT0()  asm volatile("cp.async.wait_group 0;" ::: "memory")

// ------------------------------ prep kernels -------------------------------
// block 0-1: b1eff ; 2-385: W1T fp16 ; 386-513: W2T fp16
__global__ void prep_all(const float* __restrict__ W1,
                         const float* __restrict__ b1,
                         const float* __restrict__ coeffs,
                         const float* __restrict__ W2) {
    const int b = blockIdx.x;
    if (b < 2) {
        const int j = b * 256 + threadIdx.x;
        float s = 0.f;
        #pragma unroll 8
        for (int d = 0; d < 64; ++d) s += W1[d * 512 + j];
        g_b1eff[j] = b1[j] + coeffs[0] * s;
    } else if (b < 386) {
        const int i = (b - 2) * 256 + threadIdx.x;      // 512*192
        const int n = i / 192, k = i % 192;
        g_W1T[i] = __float2half_rn(W1[(64 + k) * 512 + n]);
    } else {
        const int i = (b - 386) * 256 + threadIdx.x;    // 64*512
        const int n = i / 512, k = i % 512;
        g_W2T[i] = __float2half_rn(W2[k * 256 + n]);
    }
}
__global__ void splitT_bf(const float* __restrict__ src, bf16* __restrict__ dhi,
                          bf16* __restrict__ dlo) {
    int i = blockIdx.x * 256 + threadIdx.x;             // 768*768
    int n = i / 768, k = i % 768;
    float v = src[(long)k * 768 + n];
    bf16 h = __float2bfloat16(v);
    dhi[i] = h;
    dlo[i] = __float2bfloat16(v - __bfloat162float(h));
}
__global__ void splitX(const float* __restrict__ X) {
    int i = blockIdx.x * 256 + threadIdx.x;             // TOKENS*768
    float v = X[i];
    bf16 h = __float2bfloat16(v);
    g_Xhi[i] = h;
    g_Xlo[i] = __float2bfloat16(v - __bfloat162float(h));
}

// ---------------------- K1: qproj (bf16 3-pass split) ----------------------
// A=Xhi/lo [8192x768], B=WqT split, NT=128. Epilogue: poly -> g_P fp16.
__global__ __launch_bounds__(256, 2) void qproj(const float* __restrict__ coeffs) {
    constexpr int KORIG = 768, NT = 128;
    constexpr int CPT = KORIG / 64, NC = 3 * CPT;
    constexpr int ASZ = 128 * 128, BSZ = NT * 128, STG = ASZ + BSZ;

    extern __shared__ char sm[];
    const int tid = threadIdx.x;
    const int wid = tid >> 5, lane = tid & 31;
    const int wm = wid & 3, wn = wid >> 2;
    const int row0 = blockIdx.y * 128;
    const int col0 = blockIdx.x * NT;
    const uint32_t smb = smem_u32(sm);

    const int arow = tid >> 1, aoct0 = (tid & 1) * 4;
    const int brow = tid >> 1, boct0 = (tid & 1) * 4;
    const u16* Ah = (const u16*)g_Xhi + (long)(row0 + arow) * KORIG;
    const u16* Al = (const u16*)g_Xlo + (long)(row0 + arow) * KORIG;
    const u16* Bh = (const u16*)g_WqT_hi + (long)(col0 + brow) * KORIG;
    const u16* Bl = (const u16*)g_WqT_lo + (long)(col0 + brow) * KORIG;

    auto issue = [&](int c) {
        const int s = c % 3;
        const int third = c / CPT;
        const int kk = (c % CPT) * 64;
        const u16* a = (third == 2) ? Al : Ah;
        const u16* b = (third == 1) ? Bl : Bh;
        const uint32_t Ab = smb + s * STG;
        const uint32_t Bb = Ab + ASZ;
        #pragma unroll
        for (int i = 0; i < 4; ++i)
            cp16(Ab + swz(arow * 128 + (aoct0 + i) * 16), a + kk + (aoct0 + i) * 8);
        #pragma unroll
        for (int i = 0; i < 4; ++i)
            cp16(Bb + swz(brow * 128 + (boct0 + i) * 16), b + kk + (boct0 + i) * 8);
        CP_COMMIT();
    };

    issue(0);
    issue(1);

    float acc[2][8][4];
    #pragma unroll
    for (int mi = 0; mi < 2; ++mi)
        #pragma unroll
        for (int nt = 0; nt < 8; ++nt)
            #pragma unroll
            for (int j = 0; j < 4; ++j) acc[mi][nt][j] = 0.f;

    for (int c = 0; c < NC; ++c) {
        if (c + 1 < NC) CP_WAIT1(); else CP_WAIT0();
        __syncthreads();
        if (c + 2 < NC) issue(c + 2);

        const uint32_t Ab = smb + (c % 3) * STG;
        const uint32_t Bb = Ab + ASZ;
        #pragma unroll
        for (int ks = 0; ks < 4; ++ks) {
            uint32_t af[2][4];
            #pragma unroll
            for (int mi = 0; mi < 2; ++mi) {
                const int r = wm * 32 + mi * 16 + (lane & 15);
                ldsm4(af[mi][0], af[mi][1], af[mi][2], af[mi][3],
                      Ab + swz(r * 128 + ks * 32 + (lane >> 4) * 16));
            }
            uint32_t bfr[8][2];
            #pragma unroll
            for (int g = 0; g < 4; ++g) {
                const int nr = wn * 64 + g * 16 + (lane & 15);
                uint32_t r0, r1, r2, r3;
                ldsm4(r0, r1, r2, r3,
                      Bb + swz(nr * 128 + ks * 32 + (lane >> 4) * 16));
                bfr[2 * g][0] = r0; bfr[2 * g][1] = r2;
                bfr[2 * g + 1][0] = r1; bfr[2 * g + 1][1] = r3;
            }
            #pragma unroll
            for (int mi = 0; mi < 2; ++mi)
                #pragma unroll
                for (int nt = 0; nt < 8; ++nt)
                    mma_bf16(acc[mi][nt], af[mi][0], af[mi][1], af[mi][2],
                             af[mi][3], bfr[nt][0], bfr[nt][1]);
        }
    }

    const float c1 = coeffs[1], c2 = coeffs[2], c3 = coeffs[3];
    const float ca[3] = {c1, c2, c3};
    #pragma unroll
    for (int mi = 0; mi < 2; ++mi) {
        #pragma unroll
        for (int nt = 0; nt < 8; ++nt) {
            const int cg = col0 + wn * 64 + nt * 8 + 2 * (lane & 3);
            #pragma unroll
            for (int h = 0; h < 2; ++h) {
                const int r = row0 + wm * 32 + mi * 16 + (lane >> 2) + h * 8;
                const int head = cg >> 6, d = cg & 63;
                const long pb = (long)(r * NHEADS + head) * 192 + d;
                float x0 = fminf(fmaxf(acc[mi][nt][2 * h], -10.f), 10.f);
                float x1 = fminf(fmaxf(acc[mi][nt][2 * h + 1], -10.f), 10.f);
                float y0 = x0, y1 = x1;
                #pragma unroll
                for (int a = 0; a < 3; ++a) {
                    float f0 = fminf(fmaxf(ca[a] * y0, -1e6f), 1e6f);
                    float f1 = fminf(fmaxf(ca[a] * y1, -1e6f), 1e6f);
                    *(__half2*)&g_P[pb + a * 64] = __floats2half2_rn(f0, f1);
                    y0 *= x0; y1 *= x1;
                }
            }
        }
    }
}

// --------------------- K23: fused MLP (H stays in smem) --------------------
// smem: P 3x16KB | W1 ring 3x16KB | W2 dbl 2x16KB | Hs 2x16KB  = 160KB
__global__ __launch_bounds__(256, 1) void fused_mlp(const float* __restrict__ b2,
                                                    float* __restrict__ outf) {
    constexpr int P_OFF  = 0;
    constexpr int W1_OFF = 49152;
    constexpr int W2_OFF = 98304;
    constexpr int HS_OFF = 131072;

    extern __shared__ char sm[];
    __shared__ float sb1[512];
    __shared__ float sb2[64];

    const int tid = threadIdx.x;
    const int wid = tid >> 5, lane = tid & 31;
    const int wm = wid & 3, wn = wid >> 2;
    const int row0 = blockIdx.x * 128;
    const uint32_t smb = smem_u32(sm);

    const int arow = tid >> 1, aoct0 = (tid & 1) * 4;
    const int w2row = tid >> 2, w2oct0 = (tid & 3) * 2;
    const u16* Pp = (const u16*)g_P + (long)(row0 + arow) * 192;

    sb1[tid] = g_b1eff[tid];
    sb1[tid + 256] = g_b1eff[tid + 256];
    if (tid < 64) sb2[tid] = b2[tid];

    auto issueW1 = [&](int g) {   // chunk g = nc*3 + kc, stage = g%3
        const uint32_t dst = smb + W1_OFF + (g % 3) * 16384;
        const u16* src = (const u16*)g_W1T + (long)((g / 3) * 128 + arow) * 192
                         + (g % 3) * 64;
        #pragma unroll
        for (int i = 0; i < 4; ++i)
            cp16(dst + swz(arow * 128 + (aoct0 + i) * 16), src + (aoct0 + i) * 8);
    };
    auto issueW2 = [&](int nc) {
        const uint32_t dst = smb + W2_OFF + (nc & 1) * 16384;
        const u16* src = (const u16*)g_W2T + (long)w2row * 512 + nc * 128;
        #pragma unroll
        for (int ck = 0; ck < 2; ++ck)
            #pragma unroll
            for (int i = 0; i < 2; ++i)
                cp16(dst + ck * 8192 + swz(w2row * 128 + (w2oct0 + i) * 16),
                     src + ck * 64 + (w2oct0 + i) * 8);
    };

    // prologue: group0 = P(all) + W1 chunk0 + W2(0); group1 = W1 chunk1
    #pragma unroll
    for (int c = 0; c < 3; ++c)
        #pragma unroll
        for (int i = 0; i < 4; ++i)
            cp16(smb + P_OFF + c * 16384 + swz(arow * 128 + (aoct0 + i) * 16),
                 Pp + c * 64 + (aoct0 + i) * 8);
    issueW1(0);
    issueW2(0);
    CP_COMMIT();
    issueW1(1);
    CP_COMMIT();

    float acc2[2][4][4];
    #pragma unroll
    for (int mi = 0; mi < 2; ++mi)
        #pragma unroll
        for (int nt = 0; nt < 4; ++nt)
            #pragma unroll
            for (int j = 0; j < 4; ++j) acc2[mi][nt][j] = 0.f;

    float acc1[2][8][4];

    for (int g = 0; g < 12; ++g) {
        const int nc = g / 3, kc = g % 3;
        if (g == 11) CP_WAIT0(); else CP_WAIT1();
        __syncthreads();
        if (g + 2 <= 11) {
            issueW1(g + 2);
            if ((g + 2) % 3 == 0) issueW2((g + 2) / 3);
            CP_COMMIT();
        }
        if (kc == 0) {   // init acc1 with b1_eff
            #pragma unroll
            for (int mi = 0; mi < 2; ++mi)
                #pragma unroll
                for (int nt = 0; nt < 8; ++nt) {
                    const int cl = nc * 128 + wn * 64 + nt * 8 + 2 * (lane & 3);
                    acc1[mi][nt][0] = sb1[cl];
                    acc1[mi][nt][1] = sb1[cl + 1];
                    acc1[mi][nt][2] = sb1[cl];
                    acc1[mi][nt][3] = sb1[cl + 1];
                }
        }
        // GEMM1 chunk kc: A = P chunk kc, B = W1 stage kc
        {
            const uint32_t Ab = smb + P_OFF + kc * 16384;
            const uint32_t Bb = smb + W1_OFF + kc * 16384;
            #pragma unroll
            for (int ks = 0; ks < 4; ++ks) {
                uint32_t af[2][4];
                #pragma unroll
                for (int mi = 0; mi < 2; ++mi) {
                    const int r = wm * 32 + mi * 16 + (lane & 15);
                    ldsm4(af[mi][0], af[mi][1], af[mi][2], af[mi][3],
                          Ab + swz(r * 128 + ks * 32 + (lane >> 4) * 16));
                }
                uint32_t bfr[8][2];
                #pragma unroll
                for (int g2 = 0; g2 < 4; ++g2) {
                    const int nr = wn * 64 + g2 * 16 + (lane & 15);
                    uint32_t r0, r1, r2, r3;
                    ldsm4(r0, r1, r2, r3,
                          Bb + swz(nr * 128 + ks * 32 + (lane >> 4) * 16));
                    bfr[2 * g2][0] = r0; bfr[2 * g2][1] = r2;
                    bfr[2 * g2 + 1][0] = r1; bfr[2 * g2 + 1][1] = r3;
                }
                #pragma unroll
                for (int mi = 0; mi < 2; ++mi)
                    #pragma unroll
                    for (int nt = 0; nt < 8; ++nt)
                        mma_f16(acc1[mi][nt], af[mi][0], af[mi][1], af[mi][2],
                                af[mi][3], bfr[nt][0], bfr[nt][1]);
            }
        }
        if (kc == 2) {
            // relu -> Hs (fp16, swizzled, 2 chunks of [128x64])
            #pragma unroll
            for (int mi = 0; mi < 2; ++mi)
                #pragma unroll
                for (int nt = 0; nt < 8; ++nt) {
                    const int cg = wn * 64 + nt * 8 + 2 * (lane & 3);
                    #pragma unroll
                    for (int h = 0; h < 2; ++h) {
                        const int r = wm * 32 + mi * 16 + (lane >> 2) + h * 8;
                        float v0 = fmaxf(acc1[mi][nt][2 * h], 0.f);
                        float v1 = fmaxf(acc1[mi][nt][2 * h + 1], 0.f);
                        *(__half2*)(sm + HS_OFF + (cg >> 6) * 16384 +
                                    swz(r * 128 + (cg & 63) * 2)) =
                            __floats2half2_rn(v0, v1);
                    }
                }
            __syncthreads();
            // GEMM2: acc2 += Hs @ W2chunk  (K=128)
            const uint32_t W2b = smb + W2_OFF + (nc & 1) * 16384;
            #pragma unroll
            for (int kc2 = 0; kc2 < 2; ++kc2) {
                const uint32_t Ab2 = smb + HS_OFF + kc2 * 16384;
                const uint32_t Bb2 = W2b + kc2 * 8192;
                #pragma unroll
                for (int ks = 0; ks < 4; ++ks) {
                    uint32_t af[2][4];
                    #pragma unroll
                    for (int mi = 0; mi < 2; ++mi) {
                        const int r = wm * 32 + mi * 16 + (lane & 15);
                        ldsm4(af[mi][0], af[mi][1], af[mi][2], af[mi][3],
                              Ab2 + swz(r * 128 + ks * 32 + (lane >> 4) * 16));
                    }
                    uint32_t bfr[4][2];
                    #pragma unroll
                    for (int g2 = 0; g2 < 2; ++g2) {
                        const int nr = wn * 32 + g2 * 16 + (lane & 15);
                        uint32_t r0, r1, r2, r3;
                        ldsm4(r0, r1, r2, r3,
                              Bb2 + swz(nr * 128 + ks * 32 + (lane >> 4) * 16));
                        bfr[2 * g2][0] = r0; bfr[2 * g2][1] = r2;
                        bfr[2 * g2 + 1][0] = r1; bfr[2 * g2 + 1][1] = r3;
                    }
                    #pragma unroll
                    for (int mi = 0; mi < 2; ++mi)
                        #pragma unroll
                        for (int nt = 0; nt < 4; ++nt)
                            mma_f16(acc2[mi][nt], af[mi][0], af[mi][1],
                                    af[mi][2], af[mi][3],
                                    bfr[nt][0], bfr[nt][1]);
                }
            }
        }
    }

    // epilogue: out[t, head*64 + cg] = acc2 + b2
    #pragma unroll
    for (int mi = 0; mi < 2; ++mi)
        #pragma unroll
        for (int nt = 0; nt < 4; ++nt) {
            const int cg = wn * 32 + nt * 8 + 2 * (lane & 3);
            #pragma unroll
            for (int h = 0; h < 2; ++h) {
                const int r = row0 + wm * 32 + mi * 16 + (lane >> 2) + h * 8;
                const int t = r / NHEADS, hh = r % NHEADS;
                float2 v = make_float2(acc2[mi][nt][2 * h] + sb2[cg],
                                       acc2[mi][nt][2 * h + 1] + sb2[cg + 1]);
                *(float2*)&outf[(long)t * 768 + hh * 64 + cg] = v;
            }
        }
}

// --------------------------------- launch ----------------------------------
extern "C" void kernel_launch(void* const* d_in, const int* in_sizes, int n_in,
                              void* d_out, int out_size) {
    const float* X      = (const float*)d_in[0];
    const float* Wq     = (const float*)d_in[1];
    const float* coeffs = (const float*)d_in[2];
    const float* W1     = (const float*)d_in[3];
    const float* b1     = (const float*)d_in[4];
    const float* W2     = (const float*)d_in[5];
    const float* b2     = (const float*)d_in[6];
    float* out = (float*)d_out;

    bf16 *wqh, *wql;
    cudaGetSymbolAddress((void**)&wqh, g_WqT_hi);
    cudaGetSymbolAddress((void**)&wql, g_WqT_lo);

    prep_all<<<514, 256>>>(W1, b1, coeffs, W2);
    splitT_bf<<<768 * 768 / 256, 256>>>(Wq, wqh, wql);
    splitX<<<TOKENS * 768 / 256, 256>>>(X);

    const int smemQ = 3 * (128 * 128 + 128 * 128);   // 98304
    const int smemF = 163840;                        // 160KB
    cudaFuncSetAttribute(qproj, cudaFuncAttributeMaxDynamicSharedMemorySize, smemQ);
    cudaFuncSetAttribute(fused_mlp, cudaFuncAttributeMaxDynamicSharedMemorySize, smemF);

    dim3 g0(6, 64);     // N=768/128, M=8192/128
    qproj<<<g0, 256, smemQ>>>(coeffs);

    fused_mlp<<<ROWS_TOT / 128, 256, smemF>>>(b2, out);
}

// round 11
// speedup vs baseline: 5.3988x; 1.3988x over previous
#include <cuda_runtime.h>
#include <cuda_fp16.h>
#include <cstdint>

// ---------------------------------------------------------------------------
// AtlasAttention round 11: all-fp16 HMMA pipeline.
//   K1 (qproj): Q = X @ Wq, fp16 2-pass (X single-rounded, Wq split hi/lo);
//               epilogue poly-expand -> g_P fp16.  A tile reused for both B
//               passes within each K-chunk (12 chunks, 2-stage cp.async).
//   K23 (fused_mlp): 128-row CTA, P resident; hidden in 8 chunks of 64:
//               GEMM1(K=192) -> relu -> Hs smem -> GEMM2 (64 out cols, fp32).
//               104KB smem -> 2 CTAs/SM (vs 1 before).
// ---------------------------------------------------------------------------

#define TOKENS   8192
#define NHEADS   12
#define ROWS_TOT (TOKENS * NHEADS)   // 98304

typedef __half fp16;
typedef uint16_t u16;

__device__ fp16 g_Xh[TOKENS * 768];
__device__ fp16 g_WqT_hi[768 * 768], g_WqT_lo[768 * 768];
__device__ fp16 g_P[ROWS_TOT * 192];
__device__ fp16 g_W1T[512 * 192];          // [n<512 hidden, k<192 poly]
__device__ fp16 g_W2T[64 * 512];           // [n<64 out, k<512 hidden]
__device__ float g_b1eff[512];

// ------------------------------- helpers -----------------------------------
__device__ __forceinline__ uint32_t smem_u32(const void* p) {
    uint32_t a;
    asm("{ .reg .u64 t; cvta.to.shared.u64 t, %1; cvt.u32.u64 %0, t; }"
        : "=r"(a) : "l"(p));
    return a;
}
__device__ __forceinline__ uint32_t swz(uint32_t o) { return o ^ ((o >> 3) & 0x70); }

__device__ __forceinline__ void ldsm4(uint32_t& r0, uint32_t& r1, uint32_t& r2,
                                      uint32_t& r3, uint32_t addr) {
    asm volatile("ldmatrix.sync.aligned.m8n8.x4.shared.b16 {%0,%1,%2,%3}, [%4];"
                 : "=r"(r0), "=r"(r1), "=r"(r2), "=r"(r3) : "r"(addr));
}
__device__ __forceinline__ void mma_f16(float* d, uint32_t a0, uint32_t a1,
                                        uint32_t a2, uint32_t a3,
                                        uint32_t b0, uint32_t b1) {
    asm volatile(
        "mma.sync.aligned.m16n8k16.row.col.f32.f16.f16.f32 "
        "{%0,%1,%2,%3}, {%4,%5,%6,%7}, {%8,%9}, {%0,%1,%2,%3};"
        : "+f"(d[0]), "+f"(d[1]), "+f"(d[2]), "+f"(d[3])
        : "r"(a0), "r"(a1), "r"(a2), "r"(a3), "r"(b0), "r"(b1));
}
__device__ __forceinline__ void cp16(uint32_t dst, const void* src) {
    asm volatile("cp.async.cg.shared.global [%0], [%1], 16;"
                 :: "r"(dst), "l"(src));
}
#define CP_COMMIT() asm volatile("cp.async.commit_group;" ::: "memory")
#define CP_WAIT1()  asm volatile("cp.async.wait_group 1;" ::: "memory")
#define CP_WAIT0()  asm volatile("cp.async.wait_group 0;" ::: "memory")

// ------------------------------ prep kernel --------------------------------
// blocks: [0,2) b1eff | [2,386) W1T | [386,514) W2T | [514,2818) WqT split
//         | [2818,27394) X cast
__global__ void prep_all(const float* __restrict__ X,
                         const float* __restrict__ Wq,
                         const float* __restrict__ W1,
                         const float* __restrict__ b1,
                         const float* __restrict__ coeffs,
                         const float* __restrict__ W2) {
    const int b = blockIdx.x;
    if (b < 2) {
        const int j = b * 256 + threadIdx.x;
        float s = 0.f;
        #pragma unroll 8
        for (int d = 0; d < 64; ++d) s += W1[d * 512 + j];
        g_b1eff[j] = b1[j] + coeffs[0] * s;
    } else if (b < 386) {
        const int i = (b - 2) * 256 + threadIdx.x;        // 512*192
        const int n = i / 192, k = i % 192;
        g_W1T[i] = __float2half_rn(W1[(64 + k) * 512 + n]);
    } else if (b < 514) {
        const int i = (b - 386) * 256 + threadIdx.x;      // 64*512
        const int n = i / 512, k = i % 512;
        g_W2T[i] = __float2half_rn(W2[k * 256 + n]);
    } else if (b < 2818) {
        const int i = (b - 514) * 256 + threadIdx.x;      // 768*768
        const int n = i / 768, k = i % 768;
        float v = Wq[(long)k * 768 + n];
        fp16 h = __float2half_rn(v);
        g_WqT_hi[i] = h;
        g_WqT_lo[i] = __float2half_rn(v - __half2float(h));
    } else {
        const int i = (b - 2818) * 256 + threadIdx.x;     // TOKENS*768
        g_Xh[i] = __float2half_rn(X[i]);
    }
}

// ---------------------- K1: qproj (fp16 2-pass split) ----------------------
// 12 K-chunks of 64; per chunk: one A tile, B_hi + B_lo tiles, acc both.
// 2-stage cp.async (48KB/stage, 96KB total -> 2 CTAs/SM).
__global__ __launch_bounds__(256, 2) void qproj(const float* __restrict__ coeffs) {
    constexpr int NC = 12;
    constexpr int STG = 49152;    // A 16K | Bhi 16K | Blo 16K

    extern __shared__ char sm[];
    const int tid = threadIdx.x;
    const int wid = tid >> 5, lane = tid & 31;
    const int wm = wid & 3, wn = wid >> 2;
    const int row0 = blockIdx.y * 128;
    const int col0 = blockIdx.x * 128;
    const uint32_t smb = smem_u32(sm);

    const int arow = tid >> 1, aoct0 = (tid & 1) * 4;
    const u16* Ap = (const u16*)g_Xh + (long)(row0 + arow) * 768;
    const u16* Bh = (const u16*)g_WqT_hi + (long)(col0 + arow) * 768;
    const u16* Bl = (const u16*)g_WqT_lo + (long)(col0 + arow) * 768;

    auto issue = [&](int c) {
        const int kk = c * 64;
        const uint32_t Ab = smb + (c & 1) * STG;
        #pragma unroll
        for (int i = 0; i < 4; ++i) {
            const uint32_t so = swz(arow * 128 + (aoct0 + i) * 16);
            cp16(Ab + so,         Ap + kk + (aoct0 + i) * 8);
            cp16(Ab + 16384 + so, Bh + kk + (aoct0 + i) * 8);
            cp16(Ab + 32768 + so, Bl + kk + (aoct0 + i) * 8);
        }
        CP_COMMIT();
    };

    issue(0);

    float acc[2][8][4];
    #pragma unroll
    for (int mi = 0; mi < 2; ++mi)
        #pragma unroll
        for (int nt = 0; nt < 8; ++nt)
            #pragma unroll
            for (int j = 0; j < 4; ++j) acc[mi][nt][j] = 0.f;

    for (int c = 0; c < NC; ++c) {
        CP_WAIT0();
        __syncthreads();
        if (c + 1 < NC) issue(c + 1);

        const uint32_t Ab = smb + (c & 1) * STG;
        #pragma unroll
        for (int ks = 0; ks < 4; ++ks) {
            uint32_t af[2][4];
            #pragma unroll
            for (int mi = 0; mi < 2; ++mi) {
                const int r = wm * 32 + mi * 16 + (lane & 15);
                ldsm4(af[mi][0], af[mi][1], af[mi][2], af[mi][3],
                      Ab + swz(r * 128 + ks * 32 + (lane >> 4) * 16));
            }
            #pragma unroll
            for (int pass = 0; pass < 2; ++pass) {
                const uint32_t Bb = Ab + 16384 + pass * 16384;
                uint32_t bfr[8][2];
                #pragma unroll
                for (int g = 0; g < 4; ++g) {
                    const int nr = wn * 64 + g * 16 + (lane & 15);
                    uint32_t r0, r1, r2, r3;
                    ldsm4(r0, r1, r2, r3,
                          Bb + swz(nr * 128 + ks * 32 + (lane >> 4) * 16));
                    bfr[2 * g][0] = r0; bfr[2 * g][1] = r2;
                    bfr[2 * g + 1][0] = r1; bfr[2 * g + 1][1] = r3;
                }
                #pragma unroll
                for (int mi = 0; mi < 2; ++mi)
                    #pragma unroll
                    for (int nt = 0; nt < 8; ++nt)
                        mma_f16(acc[mi][nt], af[mi][0], af[mi][1], af[mi][2],
                                af[mi][3], bfr[nt][0], bfr[nt][1]);
            }
        }
        __syncthreads();
    }

    const float ca[3] = {coeffs[1], coeffs[2], coeffs[3]};
    #pragma unroll
    for (int mi = 0; mi < 2; ++mi) {
        #pragma unroll
        for (int nt = 0; nt < 8; ++nt) {
            const int cg = col0 + wn * 64 + nt * 8 + 2 * (lane & 3);
            #pragma unroll
            for (int h = 0; h < 2; ++h) {
                const int r = row0 + wm * 32 + mi * 16 + (lane >> 2) + h * 8;
                const int head = cg >> 6, d = cg & 63;
                const long pb = (long)(r * NHEADS + head) * 192 + d;
                float x0 = fminf(fmaxf(acc[mi][nt][2 * h], -10.f), 10.f);
                float x1 = fminf(fmaxf(acc[mi][nt][2 * h + 1], -10.f), 10.f);
                float y0 = x0, y1 = x1;
                #pragma unroll
                for (int a = 0; a < 3; ++a) {
                    float f0 = fminf(fmaxf(ca[a] * y0, -1e6f), 1e6f);
                    float f1 = fminf(fmaxf(ca[a] * y1, -1e6f), 1e6f);
                    *(__half2*)&g_P[pb + a * 64] = __floats2half2_rn(f0, f1);
                    y0 *= x0; y1 *= x1;
                }
            }
        }
    }
}

// --------------------- K23: fused MLP (H stays in smem) --------------------
// smem: P 48KB | W1 ring 3x8KB | W2 dbl 2x8KB | Hs 16KB = 104KB -> 2 CTAs/SM.
// hidden in 8 chunks of 64; 24 pipeline steps (g = nc*3 + kc).
__global__ __launch_bounds__(256, 2) void fused_mlp(const float* __restrict__ b2,
                                                    float* __restrict__ outf) {
    constexpr int P_OFF  = 0;          // 3 * 16384
    constexpr int W1_OFF = 49152;      // 3 * 8192
    constexpr int W2_OFF = 73728;      // 2 * 8192
    constexpr int HS_OFF = 90112;      // 16384

    extern __shared__ char sm[];
    __shared__ float sb1[512];
    __shared__ float sb2[64];

    const int tid = threadIdx.x;
    const int wid = tid >> 5, lane = tid & 31;
    const int wm = wid & 3, wn = wid >> 2;      // wn in 0..1
    const int row0 = blockIdx.x * 128;
    const uint32_t smb = smem_u32(sm);

    const int arow = tid >> 1, aoct0 = (tid & 1) * 4;
    const int wrow = tid >> 2, woct0 = (tid & 3) * 2;
    const u16* Pp = (const u16*)g_P + (long)(row0 + arow) * 192;

    sb1[tid] = g_b1eff[tid];
    sb1[tid + 256] = g_b1eff[tid + 256];
    if (tid < 64) sb2[tid] = b2[tid];

    auto issueW1 = [&](int g) {        // [64 hid x 64 k] tile, stage g%3
        const uint32_t dst = smb + W1_OFF + (g % 3) * 8192;
        const u16* src = (const u16*)g_W1T + (long)((g / 3) * 64 + wrow) * 192
                         + (g % 3) * 64;
        #pragma unroll
        for (int i = 0; i < 2; ++i)
            cp16(dst + swz(wrow * 128 + (woct0 + i) * 16), src + (woct0 + i) * 8);
    };
    auto issueW2 = [&](int nc) {       // [64 out x 64 hid] tile, stage nc&1
        const uint32_t dst = smb + W2_OFF + (nc & 1) * 8192;
        const u16* src = (const u16*)g_W2T + (long)wrow * 512 + nc * 64;
        #pragma unroll
        for (int i = 0; i < 2; ++i)
            cp16(dst + swz(wrow * 128 + (woct0 + i) * 16), src + (woct0 + i) * 8);
    };

    // prologue: group0 = P(all 48KB) + W1(0) + W2(0); group1 = W1(1)
    #pragma unroll
    for (int c = 0; c < 3; ++c)
        #pragma unroll
        for (int i = 0; i < 4; ++i)
            cp16(smb + P_OFF + c * 16384 + swz(arow * 128 + (aoct0 + i) * 16),
                 Pp + c * 64 + (aoct0 + i) * 8);
    issueW1(0);
    issueW2(0);
    CP_COMMIT();
    issueW1(1);
    CP_COMMIT();

    float acc2[2][4][4];
    #pragma unroll
    for (int mi = 0; mi < 2; ++mi)
        #pragma unroll
        for (int nt = 0; nt < 4; ++nt)
            #pragma unroll
            for (int j = 0; j < 4; ++j) acc2[mi][nt][j] = 0.f;

    float acc1[2][4][4];

    for (int g = 0; g < 24; ++g) {
        const int nc = g / 3, kc = g % 3;
        if (g >= 22) CP_WAIT0(); else CP_WAIT1();
        __syncthreads();
        if (g + 2 < 24) {
            issueW1(g + 2);
            if ((g + 2) % 3 == 0) issueW2((g + 2) / 3);
            CP_COMMIT();
        }
        if (kc == 0) {
            #pragma unroll
            for (int mi = 0; mi < 2; ++mi)
                #pragma unroll
                for (int nt = 0; nt < 4; ++nt) {
                    const int cl = nc * 64 + wn * 32 + nt * 8 + 2 * (lane & 3);
                    acc1[mi][nt][0] = sb1[cl];
                    acc1[mi][nt][1] = sb1[cl + 1];
                    acc1[mi][nt][2] = sb1[cl];
                    acc1[mi][nt][3] = sb1[cl + 1];
                }
        }
        // GEMM1 k-chunk kc: A = P[:, kc*64..], B = W1 stage
        {
            const uint32_t Ab = smb + P_OFF + kc * 16384;
            const uint32_t Bb = smb + W1_OFF + kc * 8192;
            #pragma unroll
            for (int ks = 0; ks < 4; ++ks) {
                uint32_t af[2][4];
                #pragma unroll
                for (int mi = 0; mi < 2; ++mi) {
                    const int r = wm * 32 + mi * 16 + (lane & 15);
                    ldsm4(af[mi][0], af[mi][1], af[mi][2], af[mi][3],
                          Ab + swz(r * 128 + ks * 32 + (lane >> 4) * 16));
                }
                uint32_t bfr[4][2];
                #pragma unroll
                for (int g2 = 0; g2 < 2; ++g2) {
                    const int nr = wn * 32 + g2 * 16 + (lane & 15);
                    uint32_t r0, r1, r2, r3;
                    ldsm4(r0, r1, r2, r3,
                          Bb + swz(nr * 128 + ks * 32 + (lane >> 4) * 16));
                    bfr[2 * g2][0] = r0; bfr[2 * g2][1] = r2;
                    bfr[2 * g2 + 1][0] = r1; bfr[2 * g2 + 1][1] = r3;
                }
                #pragma unroll
                for (int mi = 0; mi < 2; ++mi)
                    #pragma unroll
                    for (int nt = 0; nt < 4; ++nt)
                        mma_f16(acc1[mi][nt], af[mi][0], af[mi][1], af[mi][2],
                                af[mi][3], bfr[nt][0], bfr[nt][1]);
            }
        }
        if (kc == 2) {
            // relu -> Hs [128 x 64] fp16
            #pragma unroll
            for (int mi = 0; mi < 2; ++mi)
                #pragma unroll
                for (int nt = 0; nt < 4; ++nt) {
                    const int cg = wn * 32 + nt * 8 + 2 * (lane & 3);
                    #pragma unroll
                    for (int h = 0; h < 2; ++h) {
                        const int r = wm * 32 + mi * 16 + (lane >> 2) + h * 8;
                        float v0 = fmaxf(acc1[mi][nt][2 * h], 0.f);
                        float v1 = fmaxf(acc1[mi][nt][2 * h + 1], 0.f);
                        *(__half2*)(sm + HS_OFF + swz(r * 128 + cg * 2)) =
                            __floats2half2_rn(v0, v1);
                    }
                }
            __syncthreads();
            // GEMM2: acc2 += Hs[128x64] @ W2chunk[64x64]^T  (K=64)
            const uint32_t Ab2 = smb + HS_OFF;
            const uint32_t Bb2 = smb + W2_OFF + (nc & 1) * 8192;
            #pragma unroll
            for (int ks = 0; ks < 4; ++ks) {
                uint32_t af[2][4];
                #pragma unroll
                for (int mi = 0; mi < 2; ++mi) {
                    const int r = wm * 32 + mi * 16 + (lane & 15);
                    ldsm4(af[mi][0], af[mi][1], af[mi][2], af[mi][3],
                          Ab2 + swz(r * 128 + ks * 32 + (lane >> 4) * 16));
                }
                uint32_t bfr[4][2];
                #pragma unroll
                for (int g2 = 0; g2 < 2; ++g2) {
                    const int nr = wn * 32 + g2 * 16 + (lane & 15);
                    uint32_t r0, r1, r2, r3;
                    ldsm4(r0, r1, r2, r3,
                          Bb2 + swz(nr * 128 + ks * 32 + (lane >> 4) * 16));
                    bfr[2 * g2][0] = r0; bfr[2 * g2][1] = r2;
                    bfr[2 * g2 + 1][0] = r1; bfr[2 * g2 + 1][1] = r3;
                }
                #pragma unroll
                for (int mi = 0; mi < 2; ++mi)
                    #pragma unroll
                    for (int nt = 0; nt < 4; ++nt)
                        mma_f16(acc2[mi][nt], af[mi][0], af[mi][1],
                                af[mi][2], af[mi][3],
                                bfr[nt][0], bfr[nt][1]);
            }
        }
    }

    // epilogue
    #pragma unroll
    for (int mi = 0; mi < 2; ++mi)
        #pragma unroll
        for (int nt = 0; nt < 4; ++nt) {
            const int cg = wn * 32 + nt * 8 + 2 * (lane & 3);
            #pragma unroll
            for (int h = 0; h < 2; ++h) {
                const int r = row0 + wm * 32 + mi * 16 + (lane >> 2) + h * 8;
                const int t = r / NHEADS, hh = r % NHEADS;
                float2 v = make_float2(acc2[mi][nt][2 * h] + sb2[cg],
                                       acc2[mi][nt][2 * h + 1] + sb2[cg + 1]);
                *(float2*)&outf[(long)t * 768 + hh * 64 + cg] = v;
            }
        }
}

// --------------------------------- launch ----------------------------------
extern "C" void kernel_launch(void* const* d_in, const int* in_sizes, int n_in,
                              void* d_out, int out_size) {
    const float* X      = (const float*)d_in[0];
    const float* Wq     = (const float*)d_in[1];
    const float* coeffs = (const float*)d_in[2];
    const float* W1     = (const float*)d_in[3];
    const float* b1     = (const float*)d_in[4];
    const float* W2     = (const float*)d_in[5];
    const float* b2     = (const float*)d_in[6];
    float* out = (float*)d_out;

    prep_all<<<27394, 256>>>(X, Wq, W1, b1, coeffs, W2);

    const int smemQ = 2 * 49152;       // 96KB
    const int smemF = 106496;          // 104KB
    cudaFuncSetAttribute(qproj, cudaFuncAttributeMaxDynamicSharedMemorySize, smemQ);
    cudaFuncSetAttribute(fused_mlp, cudaFuncAttributeMaxDynamicSharedMemorySize, smemF);

    dim3 g0(6, 64);     // N=768/128, M=8192/128
    qproj<<<g0, 256, smemQ>>>(coeffs);

    fused_mlp<<<ROWS_TOT / 128, 256, smemF>>>(b2, out);
}

// round 13
// speedup vs baseline: 6.6865x; 1.2385x over previous
#include <cuda_runtime.h>
#include <cuda_fp16.h>
#include <cstdint>

// ---------------------------------------------------------------------------
// AtlasAttention round 12: single-pass fp16 HMMA everywhere.
//   K1 (qproj): Q = X @ Wq, plain fp16 (X and Wq each rounded once);
//               3-stage cp.async ring; epilogue poly-expand -> g_P fp16.
//   K23 (fused_mlp): 128-row CTA, P resident in smem; hidden in 8 chunks
//               of 64: GEMM1(K=192) -> relu -> Hs smem -> GEMM2 -> out fp32.
// Error model (calibrated R8-R11): four fp16 rounding sources -> ~4.9e-4.
// ---------------------------------------------------------------------------

#define TOKENS   8192
#define NHEADS   12
#define ROWS_TOT (TOKENS * NHEADS)   // 98304

typedef __half fp16;
typedef uint16_t u16;

__device__ fp16 g_Xh[TOKENS * 768];
__device__ fp16 g_WqT[768 * 768];
__device__ fp16 g_P[ROWS_TOT * 192];
__device__ fp16 g_W1T[512 * 192];          // [n<512 hidden, k<192 poly]
__device__ fp16 g_W2T[64 * 512];           // [n<64 out, k<512 hidden]
__device__ float g_b1eff[512];

// ------------------------------- helpers -----------------------------------
__device__ __forceinline__ uint32_t smem_u32(const void* p) {
    uint32_t a;
    asm("{ .reg .u64 t; cvta.to.shared.u64 t, %1; cvt.u32.u64 %0, t; }"
        : "=r"(a) : "l"(p));
    return a;
}
__device__ __forceinline__ uint32_t swz(uint32_t o) { return o ^ ((o >> 3) & 0x70); }

__device__ __forceinline__ void ldsm4(uint32_t& r0, uint32_t& r1, uint32_t& r2,
                                      uint32_t& r3, uint32_t addr) {
    asm volatile("ldmatrix.sync.aligned.m8n8.x4.shared.b16 {%0,%1,%2,%3}, [%4];"
                 : "=r"(r0), "=r"(r1), "=r"(r2), "=r"(r3) : "r"(addr));
}
__device__ __forceinline__ void mma_f16(float* d, uint32_t a0, uint32_t a1,
                                        uint32_t a2, uint32_t a3,
                                        uint32_t b0, uint32_t b1) {
    asm volatile(
        "mma.sync.aligned.m16n8k16.row.col.f32.f16.f16.f32 "
        "{%0,%1,%2,%3}, {%4,%5,%6,%7}, {%8,%9}, {%0,%1,%2,%3};"
        : "+f"(d[0]), "+f"(d[1]), "+f"(d[2]), "+f"(d[3])
        : "r"(a0), "r"(a1), "r"(a2), "r"(a3), "r"(b0), "r"(b1));
}
__device__ __forceinline__ void cp16(uint32_t dst, const void* src) {
    asm volatile("cp.async.cg.shared.global [%0], [%1], 16;"
                 :: "r"(dst), "l"(src));
}
#define CP_COMMIT() asm volatile("cp.async.commit_group;" ::: "memory")
#define CP_WAIT1()  asm volatile("cp.async.wait_group 1;" ::: "memory")
#define CP_WAIT0()  asm volatile("cp.async.wait_group 0;" ::: "memory")

// ------------------------------ prep kernel --------------------------------
// blocks: [0,2) b1eff | [2,386) W1T | [386,514) W2T | [514,2818) WqT cast
//         | [2818,8962) X cast vec4
__global__ void prep_all(const float* __restrict__ X,
                         const float* __restrict__ Wq,
                         const float* __restrict__ W1,
                         const float* __restrict__ b1,
                         const float* __restrict__ coeffs,
                         const float* __restrict__ W2) {
    const int b = blockIdx.x;
    if (b < 2) {
        const int j = b * 256 + threadIdx.x;
        float s = 0.f;
        #pragma unroll 8
        for (int d = 0; d < 64; ++d) s += W1[d * 512 + j];
        g_b1eff[j] = b1[j] + coeffs[0] * s;
    } else if (b < 386) {
        const int i = (b - 2) * 256 + threadIdx.x;        // 512*192
        const int n = i / 192, k = i % 192;
        g_W1T[i] = __float2half_rn(W1[(64 + k) * 512 + n]);
    } else if (b < 514) {
        const int i = (b - 386) * 256 + threadIdx.x;      // 64*512
        const int n = i / 512, k = i % 512;
        g_W2T[i] = __float2half_rn(W2[k * 256 + n]);
    } else if (b < 2818) {
        const int i = (b - 514) * 256 + threadIdx.x;      // 768*768
        const int n = i / 768, k = i % 768;
        g_WqT[i] = __float2half_rn(Wq[(long)k * 768 + n]);
    } else {
        const int i = (b - 2818) * 256 + threadIdx.x;     // TOKENS*768/4
        const float4 v = *(const float4*)(X + (long)i * 4);
        __half2 h0 = __floats2half2_rn(v.x, v.y);
        __half2 h1 = __floats2half2_rn(v.z, v.w);
        *(uint2*)&g_Xh[(long)i * 4] =
            make_uint2(*(uint32_t*)&h0, *(uint32_t*)&h1);
    }
}

// ---------------------- K1: qproj (single-pass fp16) -----------------------
// 12 K-chunks of 64; 3-stage cp.async ring (32KB/stage, 96KB -> 2 CTAs/SM).
__global__ __launch_bounds__(256, 2) void qproj(const float* __restrict__ coeffs) {
    constexpr int NC = 12;
    constexpr int STG = 32768;    // A 16K | B 16K

    extern __shared__ char sm[];
    const int tid = threadIdx.x;
    const int wid = tid >> 5, lane = tid & 31;
    const int wm = wid & 3, wn = wid >> 2;
    const int row0 = blockIdx.y * 128;
    const int col0 = blockIdx.x * 128;
    const uint32_t smb = smem_u32(sm);

    const int arow = tid >> 1, aoct0 = (tid & 1) * 4;
    const u16* Ap = (const u16*)g_Xh + (long)(row0 + arow) * 768;
    const u16* Bp = (const u16*)g_WqT + (long)(col0 + arow) * 768;

    auto issue = [&](int c) {
        const int kk = c * 64;
        const uint32_t Ab = smb + (c % 3) * STG;
        #pragma unroll
        for (int i = 0; i < 4; ++i) {
            const uint32_t so = swz(arow * 128 + (aoct0 + i) * 16);
            cp16(Ab + so,         Ap + kk + (aoct0 + i) * 8);
            cp16(Ab + 16384 + so, Bp + kk + (aoct0 + i) * 8);
        }
        CP_COMMIT();
    };

    issue(0);
    issue(1);

    float acc[2][8][4];
    #pragma unroll
    for (int mi = 0; mi < 2; ++mi)
        #pragma unroll
        for (int nt = 0; nt < 8; ++nt)
            #pragma unroll
            for (int j = 0; j < 4; ++j) acc[mi][nt][j] = 0.f;

    for (int c = 0; c < NC; ++c) {
        if (c + 1 < NC) CP_WAIT1(); else CP_WAIT0();
        __syncthreads();
        if (c + 2 < NC) issue(c + 2);

        const uint32_t Ab = smb + (c % 3) * STG;
        const uint32_t Bb = Ab + 16384;
        #pragma unroll
        for (int ks = 0; ks < 4; ++ks) {
            uint32_t af[2][4];
            #pragma unroll
            for (int mi = 0; mi < 2; ++mi) {
                const int r = wm * 32 + mi * 16 + (lane & 15);
                ldsm4(af[mi][0], af[mi][1], af[mi][2], af[mi][3],
                      Ab + swz(r * 128 + ks * 32 + (lane >> 4) * 16));
            }
            uint32_t bfr[8][2];
            #pragma unroll
            for (int g = 0; g < 4; ++g) {
                const int nr = wn * 64 + g * 16 + (lane & 15);
                uint32_t r0, r1, r2, r3;
                ldsm4(r0, r1, r2, r3,
                      Bb + swz(nr * 128 + ks * 32 + (lane >> 4) * 16));
                bfr[2 * g][0] = r0; bfr[2 * g][1] = r2;
                bfr[2 * g + 1][0] = r1; bfr[2 * g + 1][1] = r3;
            }
            #pragma unroll
            for (int mi = 0; mi < 2; ++mi)
                #pragma unroll
                for (int nt = 0; nt < 8; ++nt)
                    mma_f16(acc[mi][nt], af[mi][0], af[mi][1], af[mi][2],
                            af[mi][3], bfr[nt][0], bfr[nt][1]);
        }
    }

    const float ca[3] = {coeffs[1], coeffs[2], coeffs[3]};
    #pragma unroll
    for (int mi = 0; mi < 2; ++mi) {
        #pragma unroll
        for (int nt = 0; nt < 8; ++nt) {
            const int cg = col0 + wn * 64 + nt * 8 + 2 * (lane & 3);
            #pragma unroll
            for (int h = 0; h < 2; ++h) {
                const int r = row0 + wm * 32 + mi * 16 + (lane >> 2) + h * 8;
                const int head = cg >> 6, d = cg & 63;
                const long pb = (long)(r * NHEADS + head) * 192 + d;
                float x0 = fminf(fmaxf(acc[mi][nt][2 * h], -10.f), 10.f);
                float x1 = fminf(fmaxf(acc[mi][nt][2 * h + 1], -10.f), 10.f);
                float y0 = x0, y1 = x1;
                #pragma unroll
                for (int a = 0; a < 3; ++a) {
                    float f0 = fminf(fmaxf(ca[a] * y0, -1e6f), 1e6f);
                    float f1 = fminf(fmaxf(ca[a] * y1, -1e6f), 1e6f);
                    *(__half2*)&g_P[pb + a * 64] = __floats2half2_rn(f0, f1);
                    y0 *= x0; y1 *= x1;
                }
            }
        }
    }
}

// --------------------- K23: fused MLP (H stays in smem) --------------------
// smem: P 48KB | W1 ring 3x8KB | W2 dbl 2x8KB | Hs 16KB = 104KB -> 2 CTAs/SM.
__global__ __launch_bounds__(256, 2) void fused_mlp(const float* __restrict__ b2,
                                                    float* __restrict__ outf) {
    constexpr int P_OFF  = 0;          // 3 * 16384
    constexpr int W1_OFF = 49152;      // 3 * 8192
    constexpr int W2_OFF = 73728;      // 2 * 8192
    constexpr int HS_OFF = 90112;      // 16384

    extern __shared__ char sm[];
    __shared__ float sb1[512];
    __shared__ float sb2[64];

    const int tid = threadIdx.x;
    const int wid = tid >> 5, lane = tid & 31;
    const int wm = wid & 3, wn = wid >> 2;      // wn in 0..1
    const int row0 = blockIdx.x * 128;
    const uint32_t smb = smem_u32(sm);

    const int arow = tid >> 1, aoct0 = (tid & 1) * 4;
    const int wrow = tid >> 2, woct0 = (tid & 3) * 2;
    const u16* Pp = (const u16*)g_P + (long)(row0 + arow) * 192;

    sb1[tid] = g_b1eff[tid];
    sb1[tid + 256] = g_b1eff[tid + 256];
    if (tid < 64) sb2[tid] = b2[tid];

    auto issueW1 = [&](int g) {        // [64 hid x 64 k] tile, stage g%3
        const uint32_t dst = smb + W1_OFF + (g % 3) * 8192;
        const u16* src = (const u16*)g_W1T + (long)((g / 3) * 64 + wrow) * 192
                         + (g % 3) * 64;
        #pragma unroll
        for (int i = 0; i < 2; ++i)
            cp16(dst + swz(wrow * 128 + (woct0 + i) * 16), src + (woct0 + i) * 8);
    };
    auto issueW2 = [&](int nc) {       // [64 out x 64 hid] tile, stage nc&1
        const uint32_t dst = smb + W2_OFF + (nc & 1) * 8192;
        const u16* src = (const u16*)g_W2T + (long)wrow * 512 + nc * 64;
        #pragma unroll
        for (int i = 0; i < 2; ++i)
            cp16(dst + swz(wrow * 128 + (woct0 + i) * 16), src + (woct0 + i) * 8);
    };

    // prologue: group0 = P(all 48KB) + W1(0) + W2(0); group1 = W1(1)
    #pragma unroll
    for (int c = 0; c < 3; ++c)
        #pragma unroll
        for (int i = 0; i < 4; ++i)
            cp16(smb + P_OFF + c * 16384 + swz(arow * 128 + (aoct0 + i) * 16),
                 Pp + c * 64 + (aoct0 + i) * 8);
    issueW1(0);
    issueW2(0);
    CP_COMMIT();
    issueW1(1);
    CP_COMMIT();

    float acc2[2][4][4];
    #pragma unroll
    for (int mi = 0; mi < 2; ++mi)
        #pragma unroll
        for (int nt = 0; nt < 4; ++nt)
            #pragma unroll
            for (int j = 0; j < 4; ++j) acc2[mi][nt][j] = 0.f;

    float acc1[2][4][4];

    for (int g = 0; g < 24; ++g) {
        const int nc = g / 3, kc = g % 3;
        if (g >= 22) CP_WAIT0(); else CP_WAIT1();
        __syncthreads();
        if (g + 2 < 24) {
            issueW1(g + 2);
            if ((g + 2) % 3 == 0) issueW2((g + 2) / 3);
            CP_COMMIT();
        }
        if (kc == 0) {
            #pragma unroll
            for (int mi = 0; mi < 2; ++mi)
                #pragma unroll
                for (int nt = 0; nt < 4; ++nt) {
                    const int cl = nc * 64 + wn * 32 + nt * 8 + 2 * (lane & 3);
                    acc1[mi][nt][0] = sb1[cl];
                    acc1[mi][nt][1] = sb1[cl + 1];
                    acc1[mi][nt][2] = sb1[cl];
                    acc1[mi][nt][3] = sb1[cl + 1];
                }
        }
        // GEMM1 k-chunk kc: A = P[:, kc*64..], B = W1 stage
        {
            const uint32_t Ab = smb + P_OFF + kc * 16384;
            const uint32_t Bb = smb + W1_OFF + kc * 8192;
            #pragma unroll
            for (int ks = 0; ks < 4; ++ks) {
                uint32_t af[2][4];
                #pragma unroll
                for (int mi = 0; mi < 2; ++mi) {
                    const int r = wm * 32 + mi * 16 + (lane & 15);
                    ldsm4(af[mi][0], af[mi][1], af[mi][2], af[mi][3],
                          Ab + swz(r * 128 + ks * 32 + (lane >> 4) * 16));
                }
                uint32_t bfr[4][2];
                #pragma unroll
                for (int g2 = 0; g2 < 2; ++g2) {
                    const int nr = wn * 32 + g2 * 16 + (lane & 15);
                    uint32_t r0, r1, r2, r3;
                    ldsm4(r0, r1, r2, r3,
                          Bb + swz(nr * 128 + ks * 32 + (lane >> 4) * 16));
                    bfr[2 * g2][0] = r0; bfr[2 * g2][1] = r2;
                    bfr[2 * g2 + 1][0] = r1; bfr[2 * g2 + 1][1] = r3;
                }
                #pragma unroll
                for (int mi = 0; mi < 2; ++mi)
                    #pragma unroll
                    for (int nt = 0; nt < 4; ++nt)
                        mma_f16(acc1[mi][nt], af[mi][0], af[mi][1], af[mi][2],
                                af[mi][3], bfr[nt][0], bfr[nt][1]);
            }
        }
        if (kc == 2) {
            // relu -> Hs [128 x 64] fp16
            #pragma unroll
            for (int mi = 0; mi < 2; ++mi)
                #pragma unroll
                for (int nt = 0; nt < 4; ++nt) {
                    const int cg = wn * 32 + nt * 8 + 2 * (lane & 3);
                    #pragma unroll
                    for (int h = 0; h < 2; ++h) {
                        const int r = wm * 32 + mi * 16 + (lane >> 2) + h * 8;
                        float v0 = fmaxf(acc1[mi][nt][2 * h], 0.f);
                        float v1 = fmaxf(acc1[mi][nt][2 * h + 1], 0.f);
                        *(__half2*)(sm + HS_OFF + swz(r * 128 + cg * 2)) =
                            __floats2half2_rn(v0, v1);
                    }
                }
            __syncthreads();
            // GEMM2: acc2 += Hs[128x64] @ W2chunk[64x64]^T  (K=64)
            const uint32_t Ab2 = smb + HS_OFF;
            const uint32_t Bb2 = smb + W2_OFF + (nc & 1) * 8192;
            #pragma unroll
            for (int ks = 0; ks < 4; ++ks) {
                uint32_t af[2][4];
                #pragma unroll
                for (int mi = 0; mi < 2; ++mi) {
                    const int r = wm * 32 + mi * 16 + (lane & 15);
                    ldsm4(af[mi][0], af[mi][1], af[mi][2], af[mi][3],
                          Ab2 + swz(r * 128 + ks * 32 + (lane >> 4) * 16));
                }
                uint32_t bfr[4][2];
                #pragma unroll
                for (int g2 = 0; g2 < 2; ++g2) {
                    const int nr = wn * 32 + g2 * 16 + (lane & 15);
                    uint32_t r0, r1, r2, r3;
                    ldsm4(r0, r1, r2, r3,
                          Bb2 + swz(nr * 128 + ks * 32 + (lane >> 4) * 16));
                    bfr[2 * g2][0] = r0; bfr[2 * g2][1] = r2;
                    bfr[2 * g2 + 1][0] = r1; bfr[2 * g2 + 1][1] = r3;
                }
                #pragma unroll
                for (int mi = 0; mi < 2; ++mi)
                    #pragma unroll
                    for (int nt = 0; nt < 4; ++nt)
                        mma_f16(acc2[mi][nt], af[mi][0], af[mi][1],
                                af[mi][2], af[mi][3],
                                bfr[nt][0], bfr[nt][1]);
            }
        }
    }

    // epilogue
    #pragma unroll
    for (int mi = 0; mi < 2; ++mi)
        #pragma unroll
        for (int nt = 0; nt < 4; ++nt) {
            const int cg = wn * 32 + nt * 8 + 2 * (lane & 3);
            #pragma unroll
            for (int h = 0; h < 2; ++h) {
                const int r = row0 + wm * 32 + mi * 16 + (lane >> 2) + h * 8;
                const int t = r / NHEADS, hh = r % NHEADS;
                float2 v = make_float2(acc2[mi][nt][2 * h] + sb2[cg],
                                       acc2[mi][nt][2 * h + 1] + sb2[cg + 1]);
                *(float2*)&outf[(long)t * 768 + hh * 64 + cg] = v;
            }
        }
}

// --------------------------------- launch ----------------------------------
extern "C" void kernel_launch(void* const* d_in, const int* in_sizes, int n_in,
                              void* d_out, int out_size) {
    const float* X      = (const float*)d_in[0];
    const float* Wq     = (const float*)d_in[1];
    const float* coeffs = (const float*)d_in[2];
    const float* W1     = (const float*)d_in[3];
    const float* b1     = (const float*)d_in[4];
    const float* W2     = (const float*)d_in[5];
    const float* b2     = (const float*)d_in[6];
    float* out = (float*)d_out;

    prep_all<<<8962, 256>>>(X, Wq, W1, b1, coeffs, W2);

    const int smemQ = 3 * 32768;       // 96KB
    const int smemF = 106496;          // 104KB
    cudaFuncSetAttribute(qproj, cudaFuncAttributeMaxDynamicSharedMemorySize, smemQ);
    cudaFuncSetAttribute(fused_mlp, cudaFuncAttributeMaxDynamicSharedMemorySize, smemF);

    dim3 g0(6, 64);     // N=768/128, M=8192/128
    qproj<<<g0, 256, smemQ>>>(coeffs);

    fused_mlp<<<ROWS_TOT / 128, 256, smemF>>>(b2, out);
}

// round 15
// speedup vs baseline: 7.3255x; 1.0956x over previous
#include <cuda_runtime.h>
#include <cuda_fp16.h>
#include <cstdint>

// ---------------------------------------------------------------------------
// AtlasAttention round 14: fp16 HMMA; qproj 128x64 @ 3 CTA/SM; poly moved
// into fused_mlp prologue (g_P eliminated; Q fp16 is the interchange).
//   K1 (qproj): Qh = Xh @ WqT, 128x64 tiles, 3-stage cp.async, occ 3.
//   K23 (fused_mlp): prologue Q->poly->P smem; 8x(GEMM1 K=192 -> relu ->
//                    Hs smem -> GEMM2) -> out fp32.
// ---------------------------------------------------------------------------

#define TOKENS   8192
#define NHEADS   12
#define ROWS_TOT (TOKENS * NHEADS)   // 98304

typedef __half fp16;
typedef uint16_t u16;

__device__ fp16 g_Xh[TOKENS * 768];
__device__ fp16 g_WqT[768 * 768];
__device__ fp16 g_Qh[TOKENS * 768];
__device__ fp16 g_W1T[512 * 192];          // [n<512 hidden, k<192 poly]
__device__ fp16 g_W2T[64 * 512];           // [n<64 out, k<512 hidden]
__device__ float g_b1eff[512];

// ------------------------------- helpers -----------------------------------
__device__ __forceinline__ uint32_t smem_u32(const void* p) {
    uint32_t a;
    asm("{ .reg .u64 t; cvta.to.shared.u64 t, %1; cvt.u32.u64 %0, t; }"
        : "=r"(a) : "l"(p));
    return a;
}
__device__ __forceinline__ uint32_t swz(uint32_t o) { return o ^ ((o >> 3) & 0x70); }

__device__ __forceinline__ void ldsm4(uint32_t& r0, uint32_t& r1, uint32_t& r2,
                                      uint32_t& r3, uint32_t addr) {
    asm volatile("ldmatrix.sync.aligned.m8n8.x4.shared.b16 {%0,%1,%2,%3}, [%4];"
                 : "=r"(r0), "=r"(r1), "=r"(r2), "=r"(r3) : "r"(addr));
}
__device__ __forceinline__ void mma_f16(float* d, uint32_t a0, uint32_t a1,
                                        uint32_t a2, uint32_t a3,
                                        uint32_t b0, uint32_t b1) {
    asm volatile(
        "mma.sync.aligned.m16n8k16.row.col.f32.f16.f16.f32 "
        "{%0,%1,%2,%3}, {%4,%5,%6,%7}, {%8,%9}, {%0,%1,%2,%3};"
        : "+f"(d[0]), "+f"(d[1]), "+f"(d[2]), "+f"(d[3])
        : "r"(a0), "r"(a1), "r"(a2), "r"(a3), "r"(b0), "r"(b1));
}
__device__ __forceinline__ void cp16(uint32_t dst, const void* src) {
    asm volatile("cp.async.cg.shared.global [%0], [%1], 16;"
                 :: "r"(dst), "l"(src));
}
#define CP_COMMIT() asm volatile("cp.async.commit_group;" ::: "memory")
#define CP_WAIT1()  asm volatile("cp.async.wait_group 1;" ::: "memory")
#define CP_WAIT0()  asm volatile("cp.async.wait_group 0;" ::: "memory")

// ------------------------------ prep kernel --------------------------------
// blocks: [0,2) b1eff | [2,386) W1T | [386,514) W2T | [514,2818) WqT cast
//         | [2818,8962) X cast vec4
__global__ void prep_all(const float* __restrict__ X,
                         const float* __restrict__ Wq,
                         const float* __restrict__ W1,
                         const float* __restrict__ b1,
                         const float* __restrict__ coeffs,
                         const float* __restrict__ W2) {
    const int b = blockIdx.x;
    if (b < 2) {
        const int j = b * 256 + threadIdx.x;
        float s = 0.f;
        #pragma unroll 8
        for (int d = 0; d < 64; ++d) s += W1[d * 512 + j];
        g_b1eff[j] = b1[j] + coeffs[0] * s;
    } else if (b < 386) {
        const int i = (b - 2) * 256 + threadIdx.x;        // 512*192
        const int n = i / 192, k = i % 192;
        g_W1T[i] = __float2half_rn(W1[(64 + k) * 512 + n]);
    } else if (b < 514) {
        const int i = (b - 386) * 256 + threadIdx.x;      // 64*512
        const int n = i / 512, k = i % 512;
        g_W2T[i] = __float2half_rn(W2[k * 256 + n]);
    } else if (b < 2818) {
        const int i = (b - 514) * 256 + threadIdx.x;      // 768*768
        const int n = i / 768, k = i % 768;
        g_WqT[i] = __float2half_rn(Wq[(long)k * 768 + n]);
    } else {
        const int i = (b - 2818) * 256 + threadIdx.x;     // TOKENS*768/4
        const float4 v = *(const float4*)(X + (long)i * 4);
        __half2 h0 = __floats2half2_rn(v.x, v.y);
        __half2 h1 = __floats2half2_rn(v.z, v.w);
        *(uint2*)&g_Xh[(long)i * 4] =
            make_uint2(*(uint32_t*)&h0, *(uint32_t*)&h1);
    }
}

// ---------------------- K1: qproj (fp16, 128x64 tiles) ---------------------
// 12 K-chunks; 3-stage ring (24KB/stage = 72KB) -> 3 CTAs/SM (24 warps).
__global__ __launch_bounds__(256, 3) void qproj() {
    constexpr int NC = 12;
    constexpr int STG = 24576;    // A 16K | B 8K

    extern __shared__ char sm[];
    const int tid = threadIdx.x;
    const int wid = tid >> 5, lane = tid & 31;
    const int wm = wid & 3, wn = wid >> 2;      // wn 0..1
    const int row0 = blockIdx.y * 128;
    const int col0 = blockIdx.x * 64;
    const uint32_t smb = smem_u32(sm);

    const int arow = tid >> 1, aoct0 = (tid & 1) * 4;
    const int brow = tid >> 2, boct0 = (tid & 3) * 2;
    const u16* Ap = (const u16*)g_Xh + (long)(row0 + arow) * 768;
    const u16* Bp = (const u16*)g_WqT + (long)(col0 + brow) * 768;

    auto issue = [&](int c) {
        const int kk = c * 64;
        const uint32_t Ab = smb + (c % 3) * STG;
        #pragma unroll
        for (int i = 0; i < 4; ++i)
            cp16(Ab + swz(arow * 128 + (aoct0 + i) * 16),
                 Ap + kk + (aoct0 + i) * 8);
        #pragma unroll
        for (int i = 0; i < 2; ++i)
            cp16(Ab + 16384 + swz(brow * 128 + (boct0 + i) * 16),
                 Bp + kk + (boct0 + i) * 8);
        CP_COMMIT();
    };

    issue(0);
    issue(1);

    float acc[2][4][4];
    #pragma unroll
    for (int mi = 0; mi < 2; ++mi)
        #pragma unroll
        for (int nt = 0; nt < 4; ++nt)
            #pragma unroll
            for (int j = 0; j < 4; ++j) acc[mi][nt][j] = 0.f;

    for (int c = 0; c < NC; ++c) {
        if (c + 1 < NC) CP_WAIT1(); else CP_WAIT0();
        __syncthreads();
        if (c + 2 < NC) issue(c + 2);

        const uint32_t Ab = smb + (c % 3) * STG;
        const uint32_t Bb = Ab + 16384;
        #pragma unroll
        for (int ks = 0; ks < 4; ++ks) {
            uint32_t af[2][4];
            #pragma unroll
            for (int mi = 0; mi < 2; ++mi) {
                const int r = wm * 32 + mi * 16 + (lane & 15);
                ldsm4(af[mi][0], af[mi][1], af[mi][2], af[mi][3],
                      Ab + swz(r * 128 + ks * 32 + (lane >> 4) * 16));
            }
            uint32_t bfr[4][2];
            #pragma unroll
            for (int g = 0; g < 2; ++g) {
                const int nr = wn * 32 + g * 16 + (lane & 15);
                uint32_t r0, r1, r2, r3;
                ldsm4(r0, r1, r2, r3,
                      Bb + swz(nr * 128 + ks * 32 + (lane >> 4) * 16));
                bfr[2 * g][0] = r0; bfr[2 * g][1] = r2;
                bfr[2 * g + 1][0] = r1; bfr[2 * g + 1][1] = r3;
            }
            #pragma unroll
            for (int mi = 0; mi < 2; ++mi)
                #pragma unroll
                for (int nt = 0; nt < 4; ++nt)
                    mma_f16(acc[mi][nt], af[mi][0], af[mi][1], af[mi][2],
                            af[mi][3], bfr[nt][0], bfr[nt][1]);
        }
    }

    // epilogue: store q fp16, coalesced-ish half2
    #pragma unroll
    for (int mi = 0; mi < 2; ++mi)
        #pragma unroll
        for (int nt = 0; nt < 4; ++nt) {
            const int cg = col0 + wn * 32 + nt * 8 + 2 * (lane & 3);
            #pragma unroll
            for (int h = 0; h < 2; ++h) {
                const int r = row0 + wm * 32 + mi * 16 + (lane >> 2) + h * 8;
                __half2 v = __floats2half2_rn(acc[mi][nt][2 * h],
                                              acc[mi][nt][2 * h + 1]);
                *(__half2*)&g_Qh[(long)r * 768 + cg] = v;
            }
        }
}

// --------------------- K23: fused MLP (H stays in smem) --------------------
// smem: P 48KB | W1 ring 3x8KB | W2 dbl 2x8KB | Hs 16KB = 104KB -> 2 CTAs/SM.
// Prologue: Q -> poly -> P smem (vectorized STS.128).
__global__ __launch_bounds__(256, 2) void fused_mlp(const float* __restrict__ b2,
                                                    const float* __restrict__ coeffs,
                                                    float* __restrict__ outf) {
    constexpr int P_OFF  = 0;          // 3 * 16384
    constexpr int W1_OFF = 49152;      // 3 * 8192
    constexpr int W2_OFF = 73728;      // 2 * 8192
    constexpr int HS_OFF = 90112;      // 16384

    extern __shared__ char sm[];
    __shared__ float sb1[512];
    __shared__ float sb2[64];

    const int tid = threadIdx.x;
    const int wid = tid >> 5, lane = tid & 31;
    const int wm = wid & 3, wn = wid >> 2;      // wn in 0..1
    const int row0 = blockIdx.x * 128;
    const uint32_t smb = smem_u32(sm);

    const int wrow = tid >> 2, woct0 = (tid & 3) * 2;

    sb1[tid] = g_b1eff[tid];
    sb1[tid + 256] = g_b1eff[tid + 256];
    if (tid < 64) sb2[tid] = b2[tid];

    auto issueW1 = [&](int g) {        // [64 hid x 64 k] tile, stage g%3
        const uint32_t dst = smb + W1_OFF + (g % 3) * 8192;
        const u16* src = (const u16*)g_W1T + (long)((g / 3) * 64 + wrow) * 192
                         + (g % 3) * 64;
        #pragma unroll
        for (int i = 0; i < 2; ++i)
            cp16(dst + swz(wrow * 128 + (woct0 + i) * 16), src + (woct0 + i) * 8);
    };
    auto issueW2 = [&](int nc) {       // [64 out x 64 hid] tile, stage nc&1
        const uint32_t dst = smb + W2_OFF + (nc & 1) * 8192;
        const u16* src = (const u16*)g_W2T + (long)wrow * 512 + nc * 64;
        #pragma unroll
        for (int i = 0; i < 2; ++i)
            cp16(dst + swz(wrow * 128 + (woct0 + i) * 16), src + (woct0 + i) * 8);
    };

    issueW1(0);
    issueW2(0);
    CP_COMMIT();
    issueW1(1);
    CP_COMMIT();

    // ---- prologue: Q -> poly -> P smem ----
    {
        const float ca0 = coeffs[1], ca1 = coeffs[2], ca2 = coeffs[3];
        const int prow = tid >> 1;             // 0..127
        const int pd0  = (tid & 1) * 32;       // 32 q-values per thread
        const int rr = row0 + prow;
        const int t = rr / NHEADS, hd = rr % NHEADS;
        const u16* qp = (const u16*)g_Qh + (long)t * 768 + hd * 64 + pd0;
        #pragma unroll
        for (int v = 0; v < 4; ++v) {
            const uint4 raw = *(const uint4*)(qp + v * 8);
            float f[8];
            #pragma unroll
            for (int e = 0; e < 4; ++e) {
                float2 fl = __half22float2(*(((const __half2*)&raw) + e));
                f[2 * e]     = fminf(fmaxf(fl.x, -10.f), 10.f);
                f[2 * e + 1] = fminf(fmaxf(fl.y, -10.f), 10.f);
            }
            const uint32_t so = swz(prow * 128 + (pd0 + v * 8) * 2);
            #pragma unroll
            for (int a = 0; a < 3; ++a) {
                const float ca = (a == 0) ? ca0 : (a == 1) ? ca1 : ca2;
                uint32_t w[4];
                #pragma unroll
                for (int e = 0; e < 4; ++e) {
                    float y0 = f[2 * e], y1 = f[2 * e + 1];
                    float p0 = y0, p1 = y1;
                    if (a >= 1) { p0 *= y0; p1 *= y1; }
                    if (a >= 2) { p0 *= y0; p1 *= y1; }
                    __half2 o = __floats2half2_rn(
                        fminf(fmaxf(ca * p0, -1e6f), 1e6f),
                        fminf(fmaxf(ca * p1, -1e6f), 1e6f));
                    w[e] = *(uint32_t*)&o;
                }
                *(uint4*)(sm + P_OFF + a * 16384 + so) =
                    make_uint4(w[0], w[1], w[2], w[3]);
            }
        }
    }

    float acc2[2][4][4];
    #pragma unroll
    for (int mi = 0; mi < 2; ++mi)
        #pragma unroll
        for (int nt = 0; nt < 4; ++nt)
            #pragma unroll
            for (int j = 0; j < 4; ++j) acc2[mi][nt][j] = 0.f;

    float acc1[2][4][4];

    for (int g = 0; g < 24; ++g) {
        const int nc = g / 3, kc = g % 3;
        if (g >= 22) CP_WAIT0(); else CP_WAIT1();
        __syncthreads();
        if (g + 2 < 24) {
            issueW1(g + 2);
            if ((g + 2) % 3 == 0) issueW2((g + 2) / 3);
            CP_COMMIT();
        }
        if (kc == 0) {
            #pragma unroll
            for (int mi = 0; mi < 2; ++mi)
                #pragma unroll
                for (int nt = 0; nt < 4; ++nt) {
                    const int cl = nc * 64 + wn * 32 + nt * 8 + 2 * (lane & 3);
                    acc1[mi][nt][0] = sb1[cl];
                    acc1[mi][nt][1] = sb1[cl + 1];
                    acc1[mi][nt][2] = sb1[cl];
                    acc1[mi][nt][3] = sb1[cl + 1];
                }
        }
        // GEMM1 k-chunk kc: A = P[:, kc*64..], B = W1 stage
        {
            const uint32_t Ab = smb + P_OFF + kc * 16384;
            const uint32_t Bb = smb + W1_OFF + kc * 8192;
            #pragma unroll
            for (int ks = 0; ks < 4; ++ks) {
                uint32_t af[2][4];
                #pragma unroll
                for (int mi = 0; mi < 2; ++mi) {
                    const int r = wm * 32 + mi * 16 + (lane & 15);
                    ldsm4(af[mi][0], af[mi][1], af[mi][2], af[mi][3],
                          Ab + swz(r * 128 + ks * 32 + (lane >> 4) * 16));
                }
                uint32_t bfr[4][2];
                #pragma unroll
                for (int g2 = 0; g2 < 2; ++g2) {
                    const int nr = wn * 32 + g2 * 16 + (lane & 15);
                    uint32_t r0, r1, r2, r3;
                    ldsm4(r0, r1, r2, r3,
                          Bb + swz(nr * 128 + ks * 32 + (lane >> 4) * 16));
                    bfr[2 * g2][0] = r0; bfr[2 * g2][1] = r2;
                    bfr[2 * g2 + 1][0] = r1; bfr[2 * g2 + 1][1] = r3;
                }
                #pragma unroll
                for (int mi = 0; mi < 2; ++mi)
                    #pragma unroll
                    for (int nt = 0; nt < 4; ++nt)
                        mma_f16(acc1[mi][nt], af[mi][0], af[mi][1], af[mi][2],
                                af[mi][3], bfr[nt][0], bfr[nt][1]);
            }
        }
        if (kc == 2) {
            // relu -> Hs [128 x 64] fp16
            #pragma unroll
            for (int mi = 0; mi < 2; ++mi)
                #pragma unroll
                for (int nt = 0; nt < 4; ++nt) {
                    const int cg = wn * 32 + nt * 8 + 2 * (lane & 3);
                    #pragma unroll
                    for (int h = 0; h < 2; ++h) {
                        const int r = wm * 32 + mi * 16 + (lane >> 2) + h * 8;
                        float v0 = fmaxf(acc1[mi][nt][2 * h], 0.f);
                        float v1 = fmaxf(acc1[mi][nt][2 * h + 1], 0.f);
                        *(__half2*)(sm + HS_OFF + swz(r * 128 + cg * 2)) =
                            __floats2half2_rn(v0, v1);
                    }
                }
            __syncthreads();
            // GEMM2: acc2 += Hs[128x64] @ W2chunk[64x64]^T  (K=64)
            const uint32_t Ab2 = smb + HS_OFF;
            const uint32_t Bb2 = smb + W2_OFF + (nc & 1) * 8192;
            #pragma unroll
            for (int ks = 0; ks < 4; ++ks) {
                uint32_t af[2][4];
                #pragma unroll
                for (int mi = 0; mi < 2; ++mi) {
                    const int r = wm * 32 + mi * 16 + (lane & 15);
                    ldsm4(af[mi][0], af[mi][1], af[mi][2], af[mi][3],
                          Ab2 + swz(r * 128 + ks * 32 + (lane >> 4) * 16));
                }
                uint32_t bfr[4][2];
                #pragma unroll
                for (int g2 = 0; g2 < 2; ++g2) {
                    const int nr = wn * 32 + g2 * 16 + (lane & 15);
                    uint32_t r0, r1, r2, r3;
                    ldsm4(r0, r1, r2, r3,
                          Bb2 + swz(nr * 128 + ks * 32 + (lane >> 4) * 16));
                    bfr[2 * g2][0] = r0; bfr[2 * g2][1] = r2;
                    bfr[2 * g2 + 1][0] = r1; bfr[2 * g2 + 1][1] = r3;
                }
                #pragma unroll
                for (int mi = 0; mi < 2; ++mi)
                    #pragma unroll
                    for (int nt = 0; nt < 4; ++nt)
                        mma_f16(acc2[mi][nt], af[mi][0], af[mi][1],
                                af[mi][2], af[mi][3],
                                bfr[nt][0], bfr[nt][1]);
            }
        }
    }

    // epilogue
    #pragma unroll
    for (int mi = 0; mi < 2; ++mi)
        #pragma unroll
        for (int nt = 0; nt < 4; ++nt) {
            const int cg = wn * 32 + nt * 8 + 2 * (lane & 3);
            #pragma unroll
            for (int h = 0; h < 2; ++h) {
                const int r = row0 + wm * 32 + mi * 16 + (lane >> 2) + h * 8;
                const int t = r / NHEADS, hh = r % NHEADS;
                float2 v = make_float2(acc2[mi][nt][2 * h] + sb2[cg],
                                       acc2[mi][nt][2 * h + 1] + sb2[cg + 1]);
                *(float2*)&outf[(long)t * 768 + hh * 64 + cg] = v;
            }
        }
}

// --------------------------------- launch ----------------------------------
extern "C" void kernel_launch(void* const* d_in, const int* in_sizes, int n_in,
                              void* d_out, int out_size) {
    const float* X      = (const float*)d_in[0];
    const float* Wq     = (const float*)d_in[1];
    const float* coeffs = (const float*)d_in[2];
    const float* W1     = (const float*)d_in[3];
    const float* b1     = (const float*)d_in[4];
    const float* W2     = (const float*)d_in[5];
    const float* b2     = (const float*)d_in[6];
    float* out = (float*)d_out;

    prep_all<<<8962, 256>>>(X, Wq, W1, b1, coeffs, W2);

    const int smemQ = 3 * 24576;       // 72KB -> 3 CTAs/SM
    const int smemF = 106496;          // 104KB -> 2 CTAs/SM
    cudaFuncSetAttribute(qproj, cudaFuncAttributeMaxDynamicSharedMemorySize, smemQ);
    cudaFuncSetAttribute(fused_mlp, cudaFuncAttributeMaxDynamicSharedMemorySize, smemF);

    dim3 g0(12, 64);    // N=768/64, M=8192/128
    qproj<<<g0, 256, smemQ>>>();

    fused_mlp<<<ROWS_TOT / 128, 256, smemF>>>(b2, coeffs, out);
}